// round 3
// baseline (speedup 1.0000x reference)
#include <cuda_runtime.h>
#include <cstdint>
#include <cstddef>

// ---------------- problem dims ----------------
#define BATCH   256
#define SEQ     512
#define EMBD    100
#define HID     1024
#define G4      4096      // 4*HID (permuted gate columns: j = 4*h + g, g in {i,f,o,c})
#define KH      1024      // H part of K
#define KXP     128       // X part padded 100 -> 128
#define KP      1152      // total K padded (36 chunks of 32)
#define KC      32        // K chunk
#define NCHUNK  36        // KP/KC
#define NTILES  128       // 4 M-tiles x 32 N-tiles
#define MT      64        // batch rows per M-tile
#define NTN     128       // permuted cols per N-tile (= 32 h indices)
#define THREADS 256

// ---------------- smem layout (floats) ----------------
#define ASTR 36           // KC + 4 pad -> 144B rows (16B aligned, conflict-free frags)
#define BSTR 132          // 128 + 4 pad -> 528B rows (16B aligned)
#define ABUF (MT*ASTR)    // 2304
#define BBUF (KC*BSTR)    // 4224
#define SM_B0 0
#define SM_B1 (BBUF)
#define SM_A0 (2*BBUF)
#define SM_A1 (2*BBUF+ABUF)
#define SM_FLOATS (2*BBUF+2*ABUF)     // 13056 floats = 52224 bytes

// ---------------- device scratch (no allocation allowed) ----------------
__device__ float    d_X[(size_t)SEQ*BATCH*KXP];   // embedded inputs, tf32-rounded, padded
__device__ float    d_Wc[(size_t)KP*G4];          // permuted combined weights, tf32-rounded
__device__ float    d_biasp[G4];                  // permuted bias
__device__ float    d_Hb[2][BATCH*HID];           // ping-pong H state (tf32-rounded)
__device__ unsigned d_barcount;                   // monotonic grid-barrier counter

// ---------------- helpers ----------------
__device__ __forceinline__ float tf32r(float x){
    unsigned u; asm("cvt.rna.tf32.f32 %0, %1;" : "=r"(u) : "f"(x));
    return __uint_as_float(u);
}
__device__ __forceinline__ void cpa16(uint32_t dst, const float* src){
    asm volatile("cp.async.cg.shared.global [%0], [%1], 16;" :: "r"(dst), "l"(src));
}
__device__ __forceinline__ void mma8(float c[4], const unsigned a[4], const unsigned b[2]){
    asm volatile("mma.sync.aligned.m16n8k8.row.col.f32.tf32.tf32.f32 "
        "{%0,%1,%2,%3}, {%4,%5,%6,%7}, {%8,%9}, {%0,%1,%2,%3};"
        : "+f"(c[0]), "+f"(c[1]), "+f"(c[2]), "+f"(c[3])
        : "r"(a[0]), "r"(a[1]), "r"(a[2]), "r"(a[3]), "r"(b[0]), "r"(b[1]));
}
__device__ __forceinline__ float sigf(float x){ return 1.0f/(1.0f + __expf(-x)); }

// ---------------- setup kernels ----------------
__global__ void k_init(const float* __restrict__ H0){
    int i = blockIdx.x*blockDim.x + threadIdx.x;
    if (i == 0) d_barcount = 0;
    if (i < BATCH*HID) d_Hb[0][i] = tf32r(H0[i]);
}

__global__ void k_embed(const int* __restrict__ tokens, const float* __restrict__ emb){
    int i = blockIdx.x*blockDim.x + threadIdx.x;
    if (i >= SEQ*BATCH*KXP) return;
    int e = i & (KXP-1);
    int b = (i >> 7) & (BATCH-1);
    int s = i >> 15;
    float v = 0.0f;
    if (e < EMBD){
        int tok = tokens[b*SEQ + s];
        v = tf32r(emb[(size_t)tok*EMBD + e]);
    }
    d_X[i] = v;
}

__global__ void k_weights(
    const float* __restrict__ Wxi, const float* __restrict__ Whi, const float* __restrict__ bi,
    const float* __restrict__ Wxf, const float* __restrict__ Whf, const float* __restrict__ bf,
    const float* __restrict__ Wxo, const float* __restrict__ Who, const float* __restrict__ bo,
    const float* __restrict__ Wxc, const float* __restrict__ Whc, const float* __restrict__ bc)
{
    int i = blockIdx.x*blockDim.x + threadIdx.x;
    if (i >= KP*G4) return;
    int j = i & (G4-1);   // permuted col: j = 4*h + g
    int k = i >> 12;
    int h = j >> 2, g = j & 3;
    const float* Wh = (g==0)?Whi:(g==1)?Whf:(g==2)?Who:Whc;
    const float* Wx = (g==0)?Wxi:(g==1)?Wxf:(g==2)?Wxo:Wxc;
    float v = 0.0f;
    if (k < KH)               v = Wh[(size_t)k*HID + h];
    else if (k < KH + EMBD)   v = Wx[(size_t)(k-KH)*HID + h];
    d_Wc[i] = tf32r(v);
    if (k == 0){
        const float* bb = (g==0)?bi:(g==1)?bf:(g==2)?bo:bc;
        d_biasp[j] = bb[h];
    }
}

// ---------------- cp.async chunk loader ----------------
__device__ __forceinline__ void load_chunk(
    uint32_t smbase, int bufsel, int kc, int m_t, int n_t, int t,
    const float* __restrict__ Hcur, int tid)
{
    uint32_t aBase = smbase + (uint32_t)(bufsel ? SM_A1 : SM_A0)*4u;
    uint32_t bBase = smbase + (uint32_t)(bufsel ? SM_B1 : SM_B0)*4u;
    const float* asrc; int astr;
    if (kc < KH/KC){
        asrc = Hcur + (size_t)m_t*MT*HID + kc*KC;              astr = HID;
    } else {
        asrc = d_X + ((size_t)t*BATCH + m_t*MT)*KXP + (kc - KH/KC)*KC; astr = KXP;
    }
    #pragma unroll
    for (int i=0;i<2;i++){                 // A: 64 rows x 8 x 16B = 512 segs
        int seg = tid + i*THREADS;
        int r = seg >> 3, cs = (seg & 7)*4;
        cpa16(aBase + (uint32_t)(r*ASTR + cs)*4u, asrc + (size_t)r*astr + cs);
    }
    const float* bsrc = d_Wc + (size_t)kc*KC*G4 + (size_t)n_t*NTN;
    #pragma unroll
    for (int i=0;i<4;i++){                 // B: 32 rows x 32 x 16B = 1024 segs
        int seg = tid + i*THREADS;
        int kr = seg >> 5, cs = (seg & 31)*4;
        cpa16(bBase + (uint32_t)(kr*BSTR + cs)*4u, bsrc + (size_t)kr*G4 + cs);
    }
}

// ---------------- persistent LSTM scan kernel ----------------
__global__ void __launch_bounds__(THREADS,1)
lstm_persist(const float* __restrict__ C0,
             const float* __restrict__ dw,
             const float* __restrict__ db,
             float* __restrict__ out)
{
    extern __shared__ float smem[];
    const int tid  = threadIdx.x;
    const int G    = gridDim.x;
    const int lane = tid & 31, warp = tid >> 5;
    const int wm   = warp >> 2, wn = warp & 3;     // warps: 2(M) x 4(N); warp tile 32x32
    const int grp  = lane >> 2, quad = lane & 3;
    const uint32_t smbase = (uint32_t)__cvta_generic_to_shared(smem);

    int tiles[4]; int ntl = 0;
    for (int tile = blockIdx.x; tile < NTILES; tile += G) tiles[ntl++] = tile;

    const int h_l = tid & 31;     // h index within tile (0..31)
    const int b_s = tid >> 5;     // batch sub-group (0..7), 8 rows each

    float Cst[4][8];              // persistent cell state owned by this thread
    float biasf[4][4][2];         // bias fragment per tile/n8/col-pair
    for (int tl=0; tl<ntl; ++tl){
        int tile = tiles[tl]; int m_t = tile>>5, n_t = tile&31;
        for (int s=0;s<8;s++){
            int b = m_t*MT + b_s*8 + s;
            Cst[tl][s] = C0[(size_t)b*HID + n_t*32 + h_l];
        }
        for (int ni=0;ni<4;ni++){
            int col = n_t*NTN + wn*32 + ni*8 + quad*2;
            biasf[tl][ni][0] = d_biasp[col];
            biasf[tl][ni][1] = d_biasp[col+1];
        }
    }

    for (int t=0; t<SEQ; ++t){
        const float* Hcur = d_Hb[t & 1];
        float*       Hnxt = d_Hb[(t+1) & 1];

        for (int tl=0; tl<ntl; ++tl){
            int tile = tiles[tl]; int m_t = tile>>5, n_t = tile&31;

            float c[2][4][4];
            #pragma unroll
            for (int mi=0;mi<2;mi++)
            #pragma unroll
            for (int ni=0;ni<4;ni++){
                c[mi][ni][0] = biasf[tl][ni][0];
                c[mi][ni][1] = biasf[tl][ni][1];
                c[mi][ni][2] = biasf[tl][ni][0];
                c[mi][ni][3] = biasf[tl][ni][1];
            }

            // 2-stage cp.async pipeline over 36 K-chunks
            load_chunk(smbase, 0, 0, m_t, n_t, t, Hcur, tid);
            asm volatile("cp.async.commit_group;" ::: "memory");

            for (int kc=0; kc<NCHUNK; ++kc){
                if (kc + 1 < NCHUNK){
                    load_chunk(smbase, (kc+1)&1, kc+1, m_t, n_t, t, Hcur, tid);
                    asm volatile("cp.async.commit_group;" ::: "memory");
                    asm volatile("cp.async.wait_group 1;" ::: "memory");
                } else {
                    asm volatile("cp.async.wait_group 0;" ::: "memory");
                }
                __syncthreads();

                const float* As = smem + ((kc&1) ? SM_A1 : SM_A0);
                const float* Bs = smem + ((kc&1) ? SM_B1 : SM_B0);
                #pragma unroll
                for (int k8=0;k8<4;k8++){
                    int kk = k8*8;
                    unsigned a[2][4], b[4][2];
                    #pragma unroll
                    for (int mi=0;mi<2;mi++){
                        int r = wm*32 + mi*16 + grp;
                        a[mi][0] = __float_as_uint(As[r*ASTR     + kk + quad]);
                        a[mi][1] = __float_as_uint(As[(r+8)*ASTR + kk + quad]);
                        a[mi][2] = __float_as_uint(As[r*ASTR     + kk + quad + 4]);
                        a[mi][3] = __float_as_uint(As[(r+8)*ASTR + kk + quad + 4]);
                    }
                    #pragma unroll
                    for (int ni=0;ni<4;ni++){
                        int cl = wn*32 + ni*8 + grp;
                        b[ni][0] = __float_as_uint(Bs[(kk+quad)*BSTR   + cl]);
                        b[ni][1] = __float_as_uint(Bs[(kk+quad+4)*BSTR + cl]);
                    }
                    #pragma unroll
                    for (int mi=0;mi<2;mi++)
                    #pragma unroll
                    for (int ni=0;ni<4;ni++)
                        mma8(c[mi][ni], a[mi], b[ni]);
                }
                __syncthreads();
            }

            // stage gate tile [64 x 128] through smem for convenient elementwise layout
            float* gsm = smem;
            #pragma unroll
            for (int mi=0;mi<2;mi++){
                int r = wm*32 + mi*16 + grp;
                #pragma unroll
                for (int ni=0;ni<4;ni++){
                    int cl = wn*32 + ni*8 + quad*2;
                    gsm[r*NTN + cl]         = c[mi][ni][0];
                    gsm[r*NTN + cl + 1]     = c[mi][ni][1];
                    gsm[(r+8)*NTN + cl]     = c[mi][ni][2];
                    gsm[(r+8)*NTN + cl + 1] = c[mi][ni][3];
                }
            }
            __syncthreads();

            // LSTM cell update; C stays in registers, H (tf32-rounded) to global
            #pragma unroll
            for (int s=0;s<8;s++){
                int bl = b_s*8 + s;
                float gi = gsm[bl*NTN + 4*h_l + 0];
                float gf = gsm[bl*NTN + 4*h_l + 1];
                float go = gsm[bl*NTN + 4*h_l + 2];
                float gc = gsm[bl*NTN + 4*h_l + 3];
                float Cn = sigf(gf)*Cst[tl][s] + sigf(gi)*tanhf(gc);
                Cst[tl][s] = Cn;
                float Hv = sigf(go)*tanhf(Cn);
                Hnxt[(size_t)(m_t*MT + bl)*HID + n_t*32 + h_l] = tf32r(Hv);
            }
            __syncthreads();   // gates smem region is reused by next tile's cp.async
        }

        // ---- grid barrier (monotonic counter, release/acquire) ----
        __threadfence();
        __syncthreads();
        if (tid == 0){
            atomicAdd(&d_barcount, 1u);
            unsigned target = (unsigned)(t+1) * (unsigned)G;
            unsigned v;
            do {
                asm volatile("ld.acquire.gpu.u32 %0, [%1];" : "=r"(v) : "l"(&d_barcount));
            } while (v < target);
        }
        __syncthreads();
    }

    // ---- dense head: out[256,2] = H_final @ dense_w + dense_b ----
    const float* Hf = d_Hb[SEQ & 1];
    for (int tl=0; tl<ntl; ++tl){
        int tile = tiles[tl];
        if ((tile & 31) != 0) continue;     // one CTA per M-tile does the head
        int m_t = tile >> 5;
        if (tid < 128){
            int r  = m_t*MT + (tid >> 1);
            int cx = tid & 1;
            float sum = db[cx];
            const float* hr = Hf + (size_t)r*HID;
            #pragma unroll 4
            for (int k=0;k<HID;k+=4){
                float4 h4 = *reinterpret_cast<const float4*>(hr + k);
                sum += h4.x*dw[(k+0)*2+cx];
                sum += h4.y*dw[(k+1)*2+cx];
                sum += h4.z*dw[(k+2)*2+cx];
                sum += h4.w*dw[(k+3)*2+cx];
            }
            out[r*2 + cx] = sum;
        }
    }
}

// ---------------- launcher ----------------
extern "C" void kernel_launch(void* const* d_in, const int* in_sizes, int n_in,
                              void* d_out, int out_size)
{
    const int*   tokens = (const int*)  d_in[0];
    const float* H0     = (const float*)d_in[1];
    const float* C0v    = (const float*)d_in[2];
    const float* Wxi = (const float*)d_in[3],  *Whi = (const float*)d_in[4],  *bi = (const float*)d_in[5];
    const float* Wxf = (const float*)d_in[6],  *Whf = (const float*)d_in[7],  *bf = (const float*)d_in[8];
    const float* Wxo = (const float*)d_in[9],  *Who = (const float*)d_in[10], *bo = (const float*)d_in[11];
    const float* Wxc = (const float*)d_in[12], *Whc = (const float*)d_in[13], *bc = (const float*)d_in[14];
    const float* emb = (const float*)d_in[15];
    const float* dw  = (const float*)d_in[16];
    const float* db  = (const float*)d_in[17];
    float* out = (float*)d_out;

    // co-residency-safe persistent grid (<= SM count); B200 has 148 SMs -> 128
    int dev = 0; cudaGetDevice(&dev);
    int sms = 0; cudaDeviceGetAttribute(&sms, cudaDevAttrMultiProcessorCount, dev);
    int grid = (sms < NTILES) ? sms : NTILES;
    if (grid < 32) grid = 32;

    cudaFuncSetAttribute(lstm_persist, cudaFuncAttributeMaxDynamicSharedMemorySize,
                         SM_FLOATS*(int)sizeof(float));

    k_init   <<<(BATCH*HID + 255)/256, 256>>>(H0);
    k_embed  <<<(SEQ*BATCH*KXP + 255)/256, 256>>>(tokens, emb);
    k_weights<<<(KP*G4 + 255)/256, 256>>>(Wxi,Whi,bi, Wxf,Whf,bf, Wxo,Who,bo, Wxc,Whc,bc);
    lstm_persist<<<grid, THREADS, SM_FLOATS*(int)sizeof(float)>>>(C0v, dw, db, out);
}

// round 4
// speedup vs baseline: 1.0551x; 1.0551x over previous
#include <cuda_runtime.h>
#include <cstdint>
#include <cstddef>

// ---------------- problem dims ----------------
#define BATCH   256
#define SEQ     512
#define EMBD    100
#define HID     1024
#define G4      4096      // permuted gate columns: j = 4*h + g
#define KH      1024
#define KXP     128       // X part padded 100 -> 128
#define KC      32
#define NCHUNK  36        // 1152 / 32
#define NTILES  128       // 4 M-tiles x 32 N-tiles
#define MT      64
#define NTN     128
#define THREADS 256
#define STAGES  4

// ---------------- smem layout (floats) ----------------
#define ASTR 36                 // 32 + 4 pad (conflict-free A frags, 16B-aligned rows)
#define ABUF (MT*ASTR)          // 2304
#define BBUF 4096               // one B block: [quad(4)][1024] xor-swizzled
#define STG  (ABUF+BBUF)        // 6400 floats per stage
#define SM_FLOATS (STAGES*STG)  // 25600 floats = 102400 B

// ---------------- device scratch ----------------
__device__ float    d_X[(size_t)SEQ*BATCH*KXP];        // permuted-within-32 embedded X
__device__ float    d_Wc[(size_t)NCHUNK*32*4096];      // [kc][nt] fragment-layout blocks
__device__ float    d_biasp[G4];
__device__ float    d_Hb[2][BATCH*HID];                // permuted-within-32 H state
__device__ unsigned d_barc[4];                         // per-m_t-group barrier counters
__device__ unsigned d_barg;                            // fallback global barrier

// ---------------- helpers ----------------
__device__ __host__ __forceinline__ int swzf(int q){ return ((q&1)<<2) | ((q>>1)<<4); }

__device__ __forceinline__ float tf32r(float x){
    unsigned u; asm("cvt.rna.tf32.f32 %0, %1;" : "=r"(u) : "f"(x));
    return __uint_as_float(u);
}
__device__ __forceinline__ void cpa16(uint32_t dst, const float* src){
    asm volatile("cp.async.cg.shared.global [%0], [%1], 16;" :: "r"(dst), "l"(src));
}
__device__ __forceinline__ void mma8(float c[4], unsigned a0, unsigned a1, unsigned a2, unsigned a3,
                                     unsigned b0, unsigned b1){
    asm volatile("mma.sync.aligned.m16n8k8.row.col.f32.tf32.tf32.f32 "
        "{%0,%1,%2,%3}, {%4,%5,%6,%7}, {%8,%9}, {%0,%1,%2,%3};"
        : "+f"(c[0]), "+f"(c[1]), "+f"(c[2]), "+f"(c[3])
        : "r"(a0), "r"(a1), "r"(a2), "r"(a3), "r"(b0), "r"(b1));
}
__device__ __forceinline__ float f4c(const float4& v, int i){
    return i==0 ? v.x : i==1 ? v.y : i==2 ? v.z : v.w;
}
__device__ __forceinline__ float sigf(float x){ return 1.0f/(1.0f + __expf(-x)); }

// within-32 k permutation: k_local = k8*8 + q + half*4  stored at  pos = q*8 + half*4 + k8
__device__ __forceinline__ int kl_from_pos(int pos){
    int q = pos>>3, half = (pos>>2)&1, k8 = pos&3;
    return k8*8 + q + half*4;
}
__device__ __forceinline__ int pos_from_kl(int kl){
    return (kl&3)*8 + (kl&4) + (kl>>3);
}

// ---------------- setup kernels (gather style) ----------------
__global__ void k_init(const float* __restrict__ H0){
    int i = blockIdx.x*blockDim.x + threadIdx.x;
    if (i < 4) d_barc[i] = 0;
    if (i == 4) d_barg = 0;
    if (i < BATCH*HID){
        int row = i>>10, pst = i&1023;
        int k = (pst & ~31) + kl_from_pos(pst&31);
        d_Hb[0][i] = tf32r(H0[row*HID + k]);
    }
}

__global__ void k_embed(const int* __restrict__ tokens, const float* __restrict__ emb){
    int i = blockIdx.x*blockDim.x + threadIdx.x;
    if (i >= SEQ*BATCH*KXP) return;
    int p = i & (KXP-1);
    int b = (i >> 7) & (BATCH-1);
    int s = i >> 15;
    int e = (p & ~31) + kl_from_pos(p & 31);
    float v = 0.0f;
    if (e < EMBD){
        int tok = tokens[b*SEQ + s];
        v = tf32r(emb[(size_t)tok*EMBD + e]);
    }
    d_X[i] = v;
}

__global__ void k_weights(
    const float* __restrict__ Wxi, const float* __restrict__ Whi, const float* __restrict__ bi,
    const float* __restrict__ Wxf, const float* __restrict__ Whf, const float* __restrict__ bf,
    const float* __restrict__ Wxo, const float* __restrict__ Who, const float* __restrict__ bo,
    const float* __restrict__ Wxc, const float* __restrict__ Whc, const float* __restrict__ bc)
{
    int i = blockIdx.x*blockDim.x + threadIdx.x;
    if (i >= NCHUNK*32*4096) return;
    int w     = i & 4095;
    int blkid = i >> 12;
    int kc = blkid >> 5, nt = blkid & 31;
    int q  = w >> 10;
    int r2 = (w & 1023) ^ swzf(q);
    int c  = r2 >> 3, v = r2 & 7;
    int half = v >> 2, k8 = v & 3;
    int k  = kc*32 + k8*8 + q + half*4;
    int col = nt*128 + c;          // permuted col j = 4h + g
    int h = col >> 2, g = col & 3;
    const float* Wh = (g==0)?Whi:(g==1)?Whf:(g==2)?Who:Whc;
    const float* Wx = (g==0)?Wxi:(g==1)?Wxf:(g==2)?Wxo:Wxc;
    float val = 0.0f;
    if (k < KH)             val = Wh[(size_t)k*HID + h];
    else if (k < KH+EMBD)   val = Wx[(size_t)(k-KH)*HID + h];
    d_Wc[i] = tf32r(val);
    if (k == 0){
        const float* bb = (g==0)?bi:(g==1)?bf:(g==2)?bo:bc;
        d_biasp[col] = bb[h];
    }
}

// ---------------- chunk loader (one commit group: 6 cp.async per thread) ----------------
__device__ __forceinline__ void load_chunk(
    uint32_t smbase, int stage, int kc, int m_t, int n_t, int t,
    const float* __restrict__ Hcur, int tid)
{
    uint32_t bB = smbase + (uint32_t)(stage*STG)*4u;
    uint32_t aB = bB + BBUF*4u;
    // B: fully contiguous 16KB block
    const float* bsrc = d_Wc + ((size_t)(kc*32 + n_t))*4096;
    #pragma unroll
    for (int i=0;i<4;i++){
        int seg = tid + i*THREADS;
        cpa16(bB + (uint32_t)seg*16u, bsrc + seg*4);
    }
    // A: 64 rows x 32 contiguous floats (pre-permuted within 32-block)
    const float* asrc; int astr;
    if (kc < KH/KC){ asrc = Hcur + (size_t)m_t*MT*HID + kc*KC;                      astr = HID; }
    else           { asrc = d_X + ((size_t)t*BATCH + m_t*MT)*KXP + (kc-KH/KC)*KC;  astr = KXP; }
    #pragma unroll
    for (int i=0;i<2;i++){
        int seg = tid + i*THREADS;
        int r = seg>>3, cs = (seg&7)*4;
        cpa16(aB + (uint32_t)(r*ASTR + cs)*4u, asrc + (size_t)r*astr + cs);
    }
}

// ---------------- persistent LSTM scan kernel ----------------
__global__ void __launch_bounds__(THREADS,1)
lstm_persist(const float* __restrict__ C0,
             const float* __restrict__ dw,
             const float* __restrict__ db,
             float* __restrict__ out)
{
    extern __shared__ float smem[];
    const int tid  = threadIdx.x;
    const int G    = gridDim.x;
    const int lane = tid & 31, warp = tid >> 5;
    const int wm   = warp >> 2, wn = warp & 3;       // 2(M) x 4(N) warps, warp tile 32x32
    const int grp  = lane >> 2, quad = lane & 3;
    const int swz  = swzf(quad);
    const uint32_t smbase = (uint32_t)__cvta_generic_to_shared(smem);

    int tiles[2]; int ntl = 0;
    for (int tile = blockIdx.x; tile < NTILES && ntl < 2; tile += G) tiles[ntl++] = tile;
    const bool grouped = (G == NTILES);
    const int  mygrp   = tiles[0] >> 5;

    const int h_l = tid & 31;
    const int b_s = tid >> 5;

    float Cst[2][8];
    float biasf[2][4][2];
    for (int tl=0; tl<ntl; ++tl){
        int tile = tiles[tl]; int m_t = tile>>5, n_t = tile&31;
        for (int s=0;s<8;s++){
            int b = m_t*MT + b_s*8 + s;
            Cst[tl][s] = C0[(size_t)b*HID + n_t*32 + h_l];
        }
        for (int ni=0;ni<4;ni++){
            int col = n_t*NTN + wn*32 + ni*8 + quad*2;
            biasf[tl][ni][0] = d_biasp[col];
            biasf[tl][ni][1] = d_biasp[col+1];
        }
    }

    for (int t=0; t<SEQ; ++t){
        const float* Hcur = d_Hb[t & 1];
        float*       Hnxt = d_Hb[(t+1) & 1];

        for (int tl=0; tl<ntl; ++tl){
            int tile = tiles[tl]; int m_t = tile>>5, n_t = tile&31;

            float c[2][4][4];
            #pragma unroll
            for (int mi=0;mi<2;mi++)
            #pragma unroll
            for (int ni=0;ni<4;ni++){
                c[mi][ni][0] = biasf[tl][ni][0];
                c[mi][ni][1] = biasf[tl][ni][1];
                c[mi][ni][2] = biasf[tl][ni][0];
                c[mi][ni][3] = biasf[tl][ni][1];
            }

            // prologue: fill 3 stages
            #pragma unroll
            for (int pk=0; pk<STAGES-1; ++pk){
                load_chunk(smbase, pk, pk, m_t, n_t, t, Hcur, tid);
                asm volatile("cp.async.commit_group;" ::: "memory");
            }

            for (int kc=0; kc<NCHUNK; ++kc){
                if (kc + STAGES-1 < NCHUNK){
                    load_chunk(smbase, (kc+STAGES-1)&(STAGES-1), kc+STAGES-1, m_t, n_t, t, Hcur, tid);
                    asm volatile("cp.async.commit_group;" ::: "memory");
                    asm volatile("cp.async.wait_group %0;" :: "n"(STAGES-1) : "memory");
                } else {
                    asm volatile("cp.async.wait_group 0;" ::: "memory");
                }
                __syncthreads();

                const float* Bs = smem + (kc & (STAGES-1))*STG;
                const float* As = Bs + BBUF;

                // fragment loads: 16x LDS.128 per thread, conflict-free
                float4 alo[4], ahi[4], blo[4], bhi[4];
                #pragma unroll
                for (int rr=0; rr<4; rr++){
                    int row = wm*32 + rr*8 + grp;
                    const float4* ap = reinterpret_cast<const float4*>(As + row*ASTR + quad*8);
                    alo[rr] = ap[0];
                    ahi[rr] = ap[1];
                }
                #pragma unroll
                for (int ni=0; ni<4; ni++){
                    int cc = wn*32 + ni*8 + grp;
                    blo[ni] = *reinterpret_cast<const float4*>(Bs + quad*1024 + ((cc*8    ) ^ swz));
                    bhi[ni] = *reinterpret_cast<const float4*>(Bs + quad*1024 + ((cc*8 + 4) ^ swz));
                }

                #pragma unroll
                for (int k8=0; k8<4; k8++){
                    #pragma unroll
                    for (int mi=0; mi<2; mi++){
                        unsigned a0 = __float_as_uint(f4c(alo[2*mi  ], k8));
                        unsigned a1 = __float_as_uint(f4c(alo[2*mi+1], k8));
                        unsigned a2 = __float_as_uint(f4c(ahi[2*mi  ], k8));
                        unsigned a3 = __float_as_uint(f4c(ahi[2*mi+1], k8));
                        #pragma unroll
                        for (int ni=0; ni<4; ni++){
                            unsigned b0 = __float_as_uint(f4c(blo[ni], k8));
                            unsigned b1 = __float_as_uint(f4c(bhi[ni], k8));
                            mma8(c[mi][ni], a0, a1, a2, a3, b0, b1);
                        }
                    }
                }
            }

            // stage gate tile [64 x 128] through smem (reuses stage 0/1 region; safe:
            // all warps passed the final chunk's barrier, stages 0/1 data is dead)
            float* gsm = smem;
            #pragma unroll
            for (int mi=0;mi<2;mi++){
                int r = wm*32 + mi*16 + grp;
                #pragma unroll
                for (int ni=0;ni<4;ni++){
                    int cl = wn*32 + ni*8 + quad*2;
                    *reinterpret_cast<float2*>(gsm + r*NTN + cl)     = make_float2(c[mi][ni][0], c[mi][ni][1]);
                    *reinterpret_cast<float2*>(gsm + (r+8)*NTN + cl) = make_float2(c[mi][ni][2], c[mi][ni][3]);
                }
            }
            __syncthreads();

            // LSTM cell update; C in registers, H (tf32, permuted layout) to global
            const int hp = n_t*32 + pos_from_kl(h_l);
            #pragma unroll
            for (int s=0;s<8;s++){
                int bl = b_s*8 + s;
                float4 gt = *reinterpret_cast<const float4*>(gsm + bl*NTN + 4*h_l);
                float Cn = sigf(gt.y)*Cst[tl][s] + sigf(gt.x)*tanhf(gt.w);
                Cst[tl][s] = Cn;
                float Hv = sigf(gt.z)*tanhf(Cn);
                Hnxt[(size_t)(m_t*MT + bl)*HID + hp] = tf32r(Hv);
            }
            __syncthreads();   // gsm region reused by next tile/step cp.async
        }

        // ---- grid barrier (per-m_t group when fully tiled, else global) ----
        __threadfence();
        __syncthreads();
        if (tid == 0){
            unsigned v;
            if (grouped){
                atomicAdd(&d_barc[mygrp], 1u);
                unsigned target = (unsigned)(t+1) * 32u;
                do { asm volatile("ld.acquire.gpu.u32 %0, [%1];" : "=r"(v) : "l"(&d_barc[mygrp])); }
                while (v < target);
            } else {
                atomicAdd(&d_barg, 1u);
                unsigned target = (unsigned)(t+1) * (unsigned)G;
                do { asm volatile("ld.acquire.gpu.u32 %0, [%1];" : "=r"(v) : "l"(&d_barg)); }
                while (v < target);
            }
        }
        __syncthreads();
    }

    // ---- dense head: out[256,2] = H_final @ dense_w + dense_b (de-permute k) ----
    const float* Hf = d_Hb[SEQ & 1];
    for (int tl=0; tl<ntl; ++tl){
        int tile = tiles[tl];
        if ((tile & 31) != 0) continue;
        int m_t = tile >> 5;
        if (tid < 128){
            int r  = m_t*MT + (tid >> 1);
            int cx = tid & 1;
            float sum = db[cx];
            const float* hr = Hf + (size_t)r*HID;
            #pragma unroll 4
            for (int p=0;p<HID;p+=4){
                float4 h4 = *reinterpret_cast<const float4*>(hr + p);
                int q = (p>>3)&3, hf = (p>>2)&1;
                int base = (p & ~31) + q + hf*4;
                sum += h4.x*dw[(base     )*2+cx];
                sum += h4.y*dw[(base +  8)*2+cx];
                sum += h4.z*dw[(base + 16)*2+cx];
                sum += h4.w*dw[(base + 24)*2+cx];
            }
            out[r*2 + cx] = sum;
        }
    }
}

// ---------------- launcher ----------------
extern "C" void kernel_launch(void* const* d_in, const int* in_sizes, int n_in,
                              void* d_out, int out_size)
{
    const int*   tokens = (const int*)  d_in[0];
    const float* H0     = (const float*)d_in[1];
    const float* C0v    = (const float*)d_in[2];
    const float* Wxi = (const float*)d_in[3],  *Whi = (const float*)d_in[4],  *bi = (const float*)d_in[5];
    const float* Wxf = (const float*)d_in[6],  *Whf = (const float*)d_in[7],  *bf = (const float*)d_in[8];
    const float* Wxo = (const float*)d_in[9],  *Who = (const float*)d_in[10], *bo = (const float*)d_in[11];
    const float* Wxc = (const float*)d_in[12], *Whc = (const float*)d_in[13], *bc = (const float*)d_in[14];
    const float* emb = (const float*)d_in[15];
    const float* dw  = (const float*)d_in[16];
    const float* db  = (const float*)d_in[17];
    float* out = (float*)d_out;

    int dev = 0; cudaGetDevice(&dev);
    int sms = 0; cudaDeviceGetAttribute(&sms, cudaDevAttrMultiProcessorCount, dev);
    int grid = (sms < NTILES) ? sms : NTILES;   // 128 on sm_100a (148 SMs)
    if (grid < 64) grid = 64;

    cudaFuncSetAttribute(lstm_persist, cudaFuncAttributeMaxDynamicSharedMemorySize,
                         SM_FLOATS*(int)sizeof(float));

    k_init   <<<(BATCH*HID + 255)/256, 256>>>(H0);
    k_embed  <<<(SEQ*BATCH*KXP + 255)/256, 256>>>(tokens, emb);
    k_weights<<<(NCHUNK*32*4096 + 255)/256, 256>>>(Wxi,Whi,bi, Wxf,Whf,bf, Wxo,Who,bo, Wxc,Whc,bc);
    lstm_persist<<<grid, THREADS, SM_FLOATS*(int)sizeof(float)>>>(C0v, dw, db, out);
}

// round 6
// speedup vs baseline: 1.7883x; 1.6948x over previous
#include <cuda_runtime.h>
#include <cuda_fp16.h>
#include <cstdint>
#include <cstddef>

// ---------------- problem dims ----------------
#define BATCH   256
#define SEQ     512
#define EMBD    100
#define HID     1024
#define KC      64        // fp16 k-elements per chunk
#define NCHUNK  18        // 16 H-chunks + 2 X-chunks
#define NTILES  128       // 4 M-tiles x 32 N-tiles
#define MT      64
#define THREADS 512
#define STAGES  4

// ---------------- word (u32 = 2 fp16) geometry ----------------
#define HROWW 512         // u32 words per H row (1024 fp16)
#define XROWW 64          // u32 words per X row (128 fp16, padded)
#define BBLKW 4096        // u32 words per B chunk-block (64k x 128n fp16)
#define ASTRW 36          // A smem row stride in words (32 + 4 pad)
#define ABUFW (MT*ASTRW)  // 2304
#define STGW  (BBLKW+ABUFW) // 6400 words = 25.6 KB
#define SMW   (STAGES*STGW) // 25600 words = 102400 B

// ---------------- device scratch ----------------
__device__ unsigned d_X[(size_t)SEQ*BATCH*XROWW];      // fp16 pairs, k-permuted per 64-group
__device__ unsigned d_Wc[(size_t)NCHUNK*32*BBLKW];     // fp16 pairs, fragment layout
__device__ float    d_biasp[4096];                     // permuted-gate bias (col = 4h+g)
__device__ unsigned d_Hb[2][(size_t)BATCH*HROWW];      // fp16 H state, k-permuted
__device__ unsigned d_barc[4];
__device__ unsigned d_barg;

// ---------------- helpers ----------------
__device__ __forceinline__ int swzf(int q){ return ((q&1)<<2) | ((q>>1)<<4); }

// within-64-fp16 (32-word) permutation:
//   logical word w = s*8 + quad + half*4   <->   stored position p = quad*8 + half*4 + s
__device__ __forceinline__ int w_from_p(int p){
    int quad = p>>3, half = (p>>2)&1, s = p&3;
    return s*8 + quad + half*4;
}
__device__ __forceinline__ int p_from_w(int w){
    int s = w>>3, r = w&7, half = r>>2, quad = r&3;
    return quad*8 + half*4 + s;
}

__device__ __forceinline__ void cpa16(uint32_t dst, const void* src){
    asm volatile("cp.async.cg.shared.global [%0], [%1], 16;" :: "r"(dst), "l"(src));
}
__device__ __forceinline__ void mma16(float c[4], unsigned a0, unsigned a1, unsigned a2, unsigned a3,
                                      unsigned b0, unsigned b1){
    asm volatile("mma.sync.aligned.m16n8k16.row.col.f32.f16.f16.f32 "
        "{%0,%1,%2,%3}, {%4,%5,%6,%7}, {%8,%9}, {%0,%1,%2,%3};"
        : "+f"(c[0]), "+f"(c[1]), "+f"(c[2]), "+f"(c[3])
        : "r"(a0), "r"(a1), "r"(a2), "r"(a3), "r"(b0), "r"(b1));
}
__device__ __forceinline__ unsigned u4c(const uint4& v, int i){
    return i==0?v.x : i==1?v.y : i==2?v.z : v.w;
}
__device__ __forceinline__ float sigf(float x){ return 1.0f/(1.0f + __expf(-x)); }
__device__ __forceinline__ unsigned packh2(float a, float b){
    __half2 h = __floats2half2_rn(a, b);
    return *reinterpret_cast<unsigned*>(&h);
}

// ---------------- setup kernels ----------------
__global__ void k_init(const float* __restrict__ H0){
    int i = blockIdx.x*blockDim.x + threadIdx.x;
    if (i < 4) d_barc[i] = 0;
    if (i == 4) d_barg = 0;
    if (i < BATCH*HROWW){
        int row = i >> 9, p32 = i & 511;
        int group = p32 >> 5, pl = p32 & 31;
        int k = group*64 + 2*w_from_p(pl);
        d_Hb[0][i] = packh2(H0[row*HID + k], H0[row*HID + k + 1]);
    }
}

__global__ void k_embed(const int* __restrict__ tokens, const float* __restrict__ emb){
    int i = blockIdx.x*blockDim.x + threadIdx.x;
    if (i >= SEQ*BATCH*XROWW) return;
    int pw = i & 63;
    int b  = (i >> 6) & (BATCH-1);
    int st = i >> 14;
    int group = pw >> 5, pl = pw & 31;
    int e0 = group*64 + 2*w_from_p(pl);
    float f0 = 0.0f, f1 = 0.0f;
    if (e0 < EMBD){
        int tok = tokens[b*SEQ + st];
        f0 = emb[(size_t)tok*EMBD + e0];
        if (e0 + 1 < EMBD) f1 = emb[(size_t)tok*EMBD + e0 + 1];
    }
    d_X[i] = packh2(f0, f1);
}

__global__ void k_weights(
    const float* __restrict__ Wxi, const float* __restrict__ Whi, const float* __restrict__ bi,
    const float* __restrict__ Wxf, const float* __restrict__ Whf, const float* __restrict__ bf,
    const float* __restrict__ Wxo, const float* __restrict__ Who, const float* __restrict__ bo,
    const float* __restrict__ Wxc, const float* __restrict__ Whc, const float* __restrict__ bc)
{
    size_t i = (size_t)blockIdx.x*blockDim.x + threadIdx.x;
    if (i >= (size_t)NCHUNK*32*BBLKW) return;
    int wblk = (int)(i & 4095);
    int blk  = (int)(i >> 12);
    int kc = blk >> 5, nt = blk & 31;
    int quad = wblk >> 10;
    int idx  = (wblk & 1023) ^ swzf(quad);
    int col_local = idx >> 3;
    int widx = idx & 7;
    int half = widx >> 2, s = widx & 3;
    int w  = s*8 + quad + half*4;
    int k0 = kc*64 + 2*w;
    int col = nt*128 + col_local;
    int h = col >> 2, g = col & 3;
    const float* Wh = (g==0)?Whi:(g==1)?Whf:(g==2)?Who:Whc;
    const float* Wx = (g==0)?Wxi:(g==1)?Wxf:(g==2)?Wxo:Wxc;
    float f0 = 0.0f, f1 = 0.0f;
    if (k0 < 1024)            f0 = Wh[(size_t)k0*HID + h];
    else if (k0 < 1024+EMBD)  f0 = Wx[(size_t)(k0-1024)*HID + h];
    int k1 = k0 + 1;
    if (k1 < 1024)            f1 = Wh[(size_t)k1*HID + h];
    else if (k1 < 1024+EMBD)  f1 = Wx[(size_t)(k1-1024)*HID + h];
    d_Wc[i] = packh2(f0, f1);
    if (kc == 0 && w == 0){
        const float* bb = (g==0)?bi:(g==1)?bf:(g==2)?bo:bc;
        d_biasp[col] = bb[h];
    }
}

// ---------------- loaders ----------------
__device__ __forceinline__ void load_B(uint32_t smbase, int stage, int kc, int n_t, int tid){
    uint32_t bB = smbase + (uint32_t)(stage*STGW)*4u;
    const unsigned* bsrc = d_Wc + ((size_t)(kc*32 + n_t))*BBLKW;
    cpa16(bB + (uint32_t)tid*16u,            bsrc + tid*4);
    cpa16(bB + (uint32_t)(tid+THREADS)*16u,  bsrc + (tid+THREADS)*4);
}
__device__ __forceinline__ void load_A(uint32_t smbase, int stage, int kc, int m_t, int t,
                                       const unsigned* __restrict__ Hcur, int tid){
    uint32_t aB = smbase + (uint32_t)(stage*STGW + BBLKW)*4u;
    int r = tid >> 3, cw = (tid & 7)*4;
    const unsigned* src;
    if (kc < 16) src = Hcur + (size_t)(m_t*MT + r)*HROWW + kc*32 + cw;
    else         src = d_X + ((size_t)t*BATCH + m_t*MT + r)*XROWW + (kc-16)*32 + cw;
    cpa16(aB + (uint32_t)(r*ASTRW + cw)*4u, src);
}
#define CP_COMMIT() asm volatile("cp.async.commit_group;" ::: "memory")

// ---------------- persistent LSTM scan ----------------
__global__ void __launch_bounds__(THREADS,1)
lstm_persist(const float* __restrict__ C0,
             const float* __restrict__ dw,
             const float* __restrict__ db,
             float* __restrict__ out)
{
    extern __shared__ unsigned smem_u[];
    // Gate staging region: placed at stage 2 (words 12800..20991). With NCHUNK=18
    // the final chunk (kc=17) reads STAGE 1, so staging must NOT overlap stage 0/1
    // (that overlap was the R5 NaN race). Stage 2's last read is kc=16 (one barrier
    // back) and stage 3's head (words 19200..20991) last read kc=15 — both dead.
    float* gsm = reinterpret_cast<float*>(smem_u + 2*STGW);
    const int tid  = threadIdx.x;
    const int G    = gridDim.x;
    const int lane = tid & 31, warp = tid >> 5;
    const int wm   = warp >> 2, wn = warp & 3;      // 4(M) x 4(N) warps; warp tile 16x32
    const int grp  = lane >> 2, quad = lane & 3;
    const int swz  = swzf(quad);
    const uint32_t smbase = (uint32_t)__cvta_generic_to_shared(smem_u);

    int tiles[2]; int ntl = 0;
    for (int tile = blockIdx.x; tile < NTILES && ntl < 2; tile += G) tiles[ntl++] = tile;
    const bool grouped = (G == NTILES);
    const int  mygrp   = tiles[0] >> 5;

    // elementwise ownership: h-pair + 2 batch rows
    const int hp = tid & 15;        // h pair index (h = 2*hp, 2*hp+1)
    const int bg = tid >> 4;        // 0..31 -> rows 2*bg, 2*bg+1

    float Cst[2][2][2];             // [tile][row_s][hh]
    float biasf[2][4][2];
    for (int tl=0; tl<ntl; ++tl){
        int tile = tiles[tl]; int m_t = tile>>5, n_t = tile&31;
        for (int s=0;s<2;s++)
            for (int hh=0;hh<2;hh++)
                Cst[tl][s][hh] = C0[(size_t)(m_t*MT + 2*bg + s)*HID + n_t*32 + 2*hp + hh];
        for (int ni=0;ni<4;ni++){
            int col = n_t*128 + wn*32 + ni*8 + quad*2;
            biasf[tl][ni][0] = d_biasp[col];
            biasf[tl][ni][1] = d_biasp[col+1];
        }
    }

    bool pre = false;   // B for next step's tiles[0] chunks 0..2 already committed?

    for (int t=0; t<SEQ; ++t){
        const unsigned* Hcur = d_Hb[t & 1];
        unsigned*       Hnxt = d_Hb[(t+1) & 1];

        for (int tl=0; tl<ntl; ++tl){
            int tile = tiles[tl]; int m_t = tile>>5, n_t = tile&31;
            bool p0 = (tl == 0) && pre;

            float c[4][4];
            #pragma unroll
            for (int ni=0;ni<4;ni++){
                c[ni][0] = biasf[tl][ni][0];
                c[ni][1] = biasf[tl][ni][1];
                c[ni][2] = biasf[tl][ni][0];
                c[ni][3] = biasf[tl][ni][1];
            }

            // prologue
            if (p0){
                // B0..B2 already in flight (3 groups); add one A group for chunks 0..2
                #pragma unroll
                for (int p=0;p<STAGES-1;p++) load_A(smbase, p, p, m_t, t, Hcur, tid);
                CP_COMMIT();                                  // group 4
            } else {
                #pragma unroll
                for (int p=0;p<STAGES-1;p++){
                    load_B(smbase, p, p, n_t, tid);
                    load_A(smbase, p, p, m_t, t, Hcur, tid);
                    CP_COMMIT();
                }
            }

            for (int kc=0; kc<NCHUNK; ++kc){
                if (kc + STAGES-1 < NCHUNK){
                    int st = (kc + STAGES-1) & (STAGES-1);
                    load_B(smbase, st, kc+STAGES-1, n_t, tid);
                    load_A(smbase, st, kc+STAGES-1, m_t, t, Hcur, tid);
                    CP_COMMIT();
                    if (p0 && kc == 0){
                        asm volatile("cp.async.wait_group 1;" ::: "memory");
                    } else {
                        asm volatile("cp.async.wait_group 3;" ::: "memory");
                    }
                } else {
                    asm volatile("cp.async.wait_group 0;" ::: "memory");
                }
                __syncthreads();

                const unsigned* Bs = smem_u + (kc & (STAGES-1))*STGW;
                const unsigned* As = Bs + BBLKW;

                // A frags: 4x LDS.128 (rows wm*16+grp, +8), conflict-free
                int r0 = (wm*16 + grp)*ASTRW + quad*8;
                uint4 alo0 = *reinterpret_cast<const uint4*>(As + r0);
                uint4 ahi0 = *reinterpret_cast<const uint4*>(As + r0 + 4);
                uint4 alo1 = *reinterpret_cast<const uint4*>(As + r0 + 8*ASTRW);
                uint4 ahi1 = *reinterpret_cast<const uint4*>(As + r0 + 8*ASTRW + 4);
                // B frags: 8x LDS.128, xor-swizzled, conflict-free
                uint4 blo[4], bhi[4];
                #pragma unroll
                for (int ni=0; ni<4; ni++){
                    int cc = wn*32 + ni*8 + grp;
                    blo[ni] = *reinterpret_cast<const uint4*>(Bs + quad*1024 + ((cc*8    ) ^ swz));
                    bhi[ni] = *reinterpret_cast<const uint4*>(Bs + quad*1024 + ((cc*8 + 4) ^ swz));
                }
                #pragma unroll
                for (int s=0; s<4; s++){
                    unsigned a0 = u4c(alo0,s), a1 = u4c(alo1,s);
                    unsigned a2 = u4c(ahi0,s), a3 = u4c(ahi1,s);
                    #pragma unroll
                    for (int ni=0; ni<4; ni++)
                        mma16(c[ni], a0, a1, a2, a3, u4c(blo[ni],s), u4c(bhi[ni],s));
                }
            }

            // Ensure ALL warps have finished their final-chunk smem reads before
            // the gate tile overwrites any stage region (robustness barrier).
            __syncthreads();

            // stage gate tile [64 x 128] fp32 in smem (stage-2 region, dead data)
            {
                int r = wm*16 + grp;
                #pragma unroll
                for (int ni=0;ni<4;ni++){
                    int cl = wn*32 + ni*8 + quad*2;
                    *reinterpret_cast<float2*>(gsm + r*128 + cl)     = make_float2(c[ni][0], c[ni][1]);
                    *reinterpret_cast<float2*>(gsm + (r+8)*128 + cl) = make_float2(c[ni][2], c[ni][3]);
                }
            }
            __syncthreads();

            // LSTM cell update; C in registers, H (fp16 pair, permuted) to global
            const int hw = (n_t>>1)*32 + p_from_w((n_t&1)*16 + hp);
            #pragma unroll
            for (int s=0;s<2;s++){
                int row = 2*bg + s;
                float4 ga = *reinterpret_cast<const float4*>(gsm + row*128 + 8*hp);
                float4 gb = *reinterpret_cast<const float4*>(gsm + row*128 + 8*hp + 4);
                float Cn0 = sigf(ga.y)*Cst[tl][s][0] + sigf(ga.x)*tanhf(ga.w);
                float Cn1 = sigf(gb.y)*Cst[tl][s][1] + sigf(gb.x)*tanhf(gb.w);
                Cst[tl][s][0] = Cn0; Cst[tl][s][1] = Cn1;
                float Hv0 = sigf(ga.z)*tanhf(Cn0);
                float Hv1 = sigf(gb.z)*tanhf(Cn1);
                Hnxt[(size_t)(m_t*MT + row)*HROWW + hw] = packh2(Hv0, Hv1);
            }
            __syncthreads();
        }

        // prefetch next step's weights for tiles[0] BEFORE the grid barrier
        if (t + 1 < SEQ){
            int n0 = tiles[0] & 31;
            #pragma unroll
            for (int p=0;p<STAGES-1;p++){
                load_B(smbase, p, p, n0, tid);
                CP_COMMIT();
            }
            pre = true;
        } else pre = false;

        // ---- grid barrier ----
        __threadfence();
        __syncthreads();
        if (tid == 0){
            unsigned v;
            if (grouped){
                atomicAdd(&d_barc[mygrp], 1u);
                unsigned target = (unsigned)(t+1) * 32u;
                do { asm volatile("ld.acquire.gpu.u32 %0, [%1];" : "=r"(v) : "l"(&d_barc[mygrp])); }
                while (v < target);
            } else {
                atomicAdd(&d_barg, 1u);
                unsigned target = (unsigned)(t+1) * (unsigned)G;
                do { asm volatile("ld.acquire.gpu.u32 %0, [%1];" : "=r"(v) : "l"(&d_barg)); }
                while (v < target);
            }
        }
        __syncthreads();
    }

    // ---- dense head: out[256,2] = H_final @ dense_w + dense_b (de-permute k) ----
    const unsigned* Hf = d_Hb[SEQ & 1];
    for (int tl=0; tl<ntl; ++tl){
        int tile = tiles[tl];
        if ((tile & 31) != 0) continue;
        int m_t = tile >> 5;
        if (tid < 128){
            int r  = m_t*MT + (tid >> 1);
            int cx = tid & 1;
            float sum = db[cx];
            const __half2* hr = reinterpret_cast<const __half2*>(Hf + (size_t)r*HROWW);
            for (int wp=0; wp<HROWW; ++wp){
                int group = wp>>5, pl = wp&31;
                int q = pl>>3, hf = (pl>>2)&1, s = pl&3;
                int k = group*64 + 2*(s*8 + q + hf*4);
                __half2 hv = hr[wp];
                sum += __low2float(hv)*dw[k*2 + cx] + __high2float(hv)*dw[(k+1)*2 + cx];
            }
            out[r*2 + cx] = sum;
        }
    }
}

// ---------------- launcher ----------------
extern "C" void kernel_launch(void* const* d_in, const int* in_sizes, int n_in,
                              void* d_out, int out_size)
{
    const int*   tokens = (const int*)  d_in[0];
    const float* H0     = (const float*)d_in[1];
    const float* C0v    = (const float*)d_in[2];
    const float* Wxi = (const float*)d_in[3],  *Whi = (const float*)d_in[4],  *bi = (const float*)d_in[5];
    const float* Wxf = (const float*)d_in[6],  *Whf = (const float*)d_in[7],  *bf = (const float*)d_in[8];
    const float* Wxo = (const float*)d_in[9],  *Who = (const float*)d_in[10], *bo = (const float*)d_in[11];
    const float* Wxc = (const float*)d_in[12], *Whc = (const float*)d_in[13], *bc = (const float*)d_in[14];
    const float* emb = (const float*)d_in[15];
    const float* dw  = (const float*)d_in[16];
    const float* db  = (const float*)d_in[17];
    float* out = (float*)d_out;

    int dev = 0; cudaGetDevice(&dev);
    int sms = 0; cudaDeviceGetAttribute(&sms, cudaDevAttrMultiProcessorCount, dev);
    int grid = (sms < NTILES) ? sms : NTILES;   // 128 on sm_100a (148 SMs) -> 1 tile/CTA
    if (grid < 64) grid = 64;

    cudaFuncSetAttribute(lstm_persist, cudaFuncAttributeMaxDynamicSharedMemorySize,
                         SMW*(int)sizeof(unsigned));

    k_init   <<<(BATCH*HROWW + 255)/256, 256>>>(H0);
    k_embed  <<<(SEQ*BATCH*XROWW + 255)/256, 256>>>(tokens, emb);
    {
        size_t nw = (size_t)NCHUNK*32*BBLKW;
        k_weights<<<(unsigned)((nw + 255)/256), 256>>>(Wxi,Whi,bi, Wxf,Whf,bf, Wxo,Who,bo, Wxc,Whc,bc);
    }
    lstm_persist<<<grid, THREADS, SMW*(int)sizeof(unsigned)>>>(C0v, dw, db, out);
}

// round 7
// speedup vs baseline: 1.7893x; 1.0006x over previous
#include <cuda_runtime.h>
#include <cuda_fp16.h>
#include <cstdint>
#include <cstddef>

// ---------------- problem dims ----------------
#define BATCH   256
#define SEQ     512
#define EMBD    100
#define HID     1024
#define KC      64        // fp16 k-elements per chunk
#define NCHUNK  18        // 16 H-chunks + 2 X-chunks
#define NTILES  128       // 4 M-tiles x 32 N-tiles
#define MT      64
#define THREADS 512
#define STAGES  4

// ---------------- word (u32 = 2 fp16) geometry ----------------
#define HROWW 512         // u32 words per H row (1024 fp16)
#define XROWW 64          // u32 words per X row (128 fp16, padded)
#define BBLKW 4096        // u32 words per B chunk-block (64k x 128n fp16)
#define ASTRW 36          // A smem row stride in words (32 + 4 pad)
#define ABUFW (MT*ASTRW)  // 2304
#define STGW  (BBLKW+ABUFW) // 6400 words = 25.6 KB
#define SMW   (STAGES*STGW) // 25600 words = 102400 B

// ---------------- device scratch ----------------
__device__ unsigned d_X[(size_t)SEQ*BATCH*XROWW];      // fp16 pairs, k-permuted per 64-group
__device__ unsigned d_Wc[(size_t)NCHUNK*32*BBLKW];     // fp16 pairs, fragment layout
__device__ float    d_biasp[4096];                     // permuted-gate bias (col = 4h+g)
__device__ unsigned d_Hb[2][(size_t)BATCH*HROWW];      // fp16 H state, k-permuted
__device__ unsigned d_barc[4];
__device__ unsigned d_barg;

// ---------------- helpers ----------------
__device__ __forceinline__ int swzf(int q){ return ((q&1)<<2) | ((q>>1)<<4); }

// within-64-fp16 (32-word) permutation:
//   logical word w = s*8 + quad + half*4   <->   stored position p = quad*8 + half*4 + s
__device__ __forceinline__ int w_from_p(int p){
    int quad = p>>3, half = (p>>2)&1, s = p&3;
    return s*8 + quad + half*4;
}
__device__ __forceinline__ int p_from_w(int w){
    int s = w>>3, r = w&7, half = r>>2, quad = r&3;
    return quad*8 + half*4 + s;
}

__device__ __forceinline__ void cpa16(uint32_t dst, const void* src){
    asm volatile("cp.async.cg.shared.global [%0], [%1], 16;" :: "r"(dst), "l"(src));
}
__device__ __forceinline__ void mma16(float c[4], unsigned a0, unsigned a1, unsigned a2, unsigned a3,
                                      unsigned b0, unsigned b1){
    asm volatile("mma.sync.aligned.m16n8k16.row.col.f32.f16.f16.f32 "
        "{%0,%1,%2,%3}, {%4,%5,%6,%7}, {%8,%9}, {%0,%1,%2,%3};"
        : "+f"(c[0]), "+f"(c[1]), "+f"(c[2]), "+f"(c[3])
        : "r"(a0), "r"(a1), "r"(a2), "r"(a3), "r"(b0), "r"(b1));
}
__device__ __forceinline__ unsigned u4c(const uint4& v, int i){
    return i==0?v.x : i==1?v.y : i==2?v.z : v.w;
}
__device__ __forceinline__ float sigf(float x){ return 1.0f/(1.0f + __expf(-x)); }
__device__ __forceinline__ unsigned packh2(float a, float b){
    __half2 h = __floats2half2_rn(a, b);
    return *reinterpret_cast<unsigned*>(&h);
}

// ---------------- setup kernels ----------------
__global__ void k_init(const float* __restrict__ H0){
    int i = blockIdx.x*blockDim.x + threadIdx.x;
    if (i < 4) d_barc[i] = 0;
    if (i == 4) d_barg = 0;
    if (i < BATCH*HROWW){
        int row = i >> 9, p32 = i & 511;
        int group = p32 >> 5, pl = p32 & 31;
        int k = group*64 + 2*w_from_p(pl);
        d_Hb[0][i] = packh2(H0[row*HID + k], H0[row*HID + k + 1]);
    }
}

__global__ void k_embed(const int* __restrict__ tokens, const float* __restrict__ emb){
    int i = blockIdx.x*blockDim.x + threadIdx.x;
    if (i >= SEQ*BATCH*XROWW) return;
    int pw = i & 63;
    int b  = (i >> 6) & (BATCH-1);
    int st = i >> 14;
    int group = pw >> 5, pl = pw & 31;
    int e0 = group*64 + 2*w_from_p(pl);
    float f0 = 0.0f, f1 = 0.0f;
    if (e0 < EMBD){
        int tok = tokens[b*SEQ + st];
        f0 = emb[(size_t)tok*EMBD + e0];
        if (e0 + 1 < EMBD) f1 = emb[(size_t)tok*EMBD + e0 + 1];
    }
    d_X[i] = packh2(f0, f1);
}

__global__ void k_weights(
    const float* __restrict__ Wxi, const float* __restrict__ Whi, const float* __restrict__ bi,
    const float* __restrict__ Wxf, const float* __restrict__ Whf, const float* __restrict__ bf,
    const float* __restrict__ Wxo, const float* __restrict__ Who, const float* __restrict__ bo,
    const float* __restrict__ Wxc, const float* __restrict__ Whc, const float* __restrict__ bc)
{
    size_t i = (size_t)blockIdx.x*blockDim.x + threadIdx.x;
    if (i >= (size_t)NCHUNK*32*BBLKW) return;
    int wblk = (int)(i & 4095);
    int blk  = (int)(i >> 12);
    int kc = blk >> 5, nt = blk & 31;
    int quad = wblk >> 10;
    int idx  = (wblk & 1023) ^ swzf(quad);
    int col_local = idx >> 3;
    int widx = idx & 7;
    int half = widx >> 2, s = widx & 3;
    int w  = s*8 + quad + half*4;
    int k0 = kc*64 + 2*w;
    int col = nt*128 + col_local;
    int h = col >> 2, g = col & 3;
    const float* Wh = (g==0)?Whi:(g==1)?Whf:(g==2)?Who:Whc;
    const float* Wx = (g==0)?Wxi:(g==1)?Wxf:(g==2)?Wxo:Wxc;
    float f0 = 0.0f, f1 = 0.0f;
    if (k0 < 1024)            f0 = Wh[(size_t)k0*HID + h];
    else if (k0 < 1024+EMBD)  f0 = Wx[(size_t)(k0-1024)*HID + h];
    int k1 = k0 + 1;
    if (k1 < 1024)            f1 = Wh[(size_t)k1*HID + h];
    else if (k1 < 1024+EMBD)  f1 = Wx[(size_t)(k1-1024)*HID + h];
    d_Wc[i] = packh2(f0, f1);
    if (kc == 0 && w == 0){
        const float* bb = (g==0)?bi:(g==1)?bf:(g==2)?bo:bc;
        d_biasp[col] = bb[h];
    }
}

// ---------------- loaders ----------------
__device__ __forceinline__ void load_B(uint32_t smbase, int stage, int kc, int n_t, int tid){
    uint32_t bB = smbase + (uint32_t)(stage*STGW)*4u;
    const unsigned* bsrc = d_Wc + ((size_t)(kc*32 + n_t))*BBLKW;
    cpa16(bB + (uint32_t)tid*16u,            bsrc + tid*4);
    cpa16(bB + (uint32_t)(tid+THREADS)*16u,  bsrc + (tid+THREADS)*4);
}
__device__ __forceinline__ void load_A(uint32_t smbase, int stage, int kc, int m_t, int t,
                                       const unsigned* __restrict__ Hcur, int tid){
    uint32_t aB = smbase + (uint32_t)(stage*STGW + BBLKW)*4u;
    int r = tid >> 3, cw = (tid & 7)*4;
    const unsigned* src;
    if (kc < 16) src = Hcur + (size_t)(m_t*MT + r)*HROWW + kc*32 + cw;
    else         src = d_X + ((size_t)t*BATCH + m_t*MT + r)*XROWW + (kc-16)*32 + cw;
    cpa16(aB + (uint32_t)(r*ASTRW + cw)*4u, src);
}
#define CP_COMMIT() asm volatile("cp.async.commit_group;" ::: "memory")

// ---------------- persistent LSTM scan ----------------
__global__ void __launch_bounds__(THREADS,1)
lstm_persist(const float* __restrict__ C0,
             const float* __restrict__ dw,
             const float* __restrict__ db,
             float* __restrict__ out)
{
    extern __shared__ unsigned smem_u[];
    // Gate staging region: placed at stage 2 (words 12800..20991). With NCHUNK=18
    // the final chunk (kc=17) reads STAGE 1, so staging must NOT overlap stage 0/1
    // (that overlap was the R5 NaN race). Stage 2's last read is kc=16 (one barrier
    // back) and stage 3's head (words 19200..20991) last read kc=15 — both dead.
    float* gsm = reinterpret_cast<float*>(smem_u + 2*STGW);
    const int tid  = threadIdx.x;
    const int G    = gridDim.x;
    const int lane = tid & 31, warp = tid >> 5;
    const int wm   = warp >> 2, wn = warp & 3;      // 4(M) x 4(N) warps; warp tile 16x32
    const int grp  = lane >> 2, quad = lane & 3;
    const int swz  = swzf(quad);
    const uint32_t smbase = (uint32_t)__cvta_generic_to_shared(smem_u);

    int tiles[2]; int ntl = 0;
    for (int tile = blockIdx.x; tile < NTILES && ntl < 2; tile += G) tiles[ntl++] = tile;
    const bool grouped = (G == NTILES);
    const int  mygrp   = tiles[0] >> 5;

    // elementwise ownership: h-pair + 2 batch rows
    const int hp = tid & 15;        // h pair index (h = 2*hp, 2*hp+1)
    const int bg = tid >> 4;        // 0..31 -> rows 2*bg, 2*bg+1

    float Cst[2][2][2];             // [tile][row_s][hh]
    float biasf[2][4][2];
    for (int tl=0; tl<ntl; ++tl){
        int tile = tiles[tl]; int m_t = tile>>5, n_t = tile&31;
        for (int s=0;s<2;s++)
            for (int hh=0;hh<2;hh++)
                Cst[tl][s][hh] = C0[(size_t)(m_t*MT + 2*bg + s)*HID + n_t*32 + 2*hp + hh];
        for (int ni=0;ni<4;ni++){
            int col = n_t*128 + wn*32 + ni*8 + quad*2;
            biasf[tl][ni][0] = d_biasp[col];
            biasf[tl][ni][1] = d_biasp[col+1];
        }
    }

    bool pre = false;   // B for next step's tiles[0] chunks 0..2 already committed?

    for (int t=0; t<SEQ; ++t){
        const unsigned* Hcur = d_Hb[t & 1];
        unsigned*       Hnxt = d_Hb[(t+1) & 1];

        for (int tl=0; tl<ntl; ++tl){
            int tile = tiles[tl]; int m_t = tile>>5, n_t = tile&31;
            bool p0 = (tl == 0) && pre;

            float c[4][4];
            #pragma unroll
            for (int ni=0;ni<4;ni++){
                c[ni][0] = biasf[tl][ni][0];
                c[ni][1] = biasf[tl][ni][1];
                c[ni][2] = biasf[tl][ni][0];
                c[ni][3] = biasf[tl][ni][1];
            }

            // prologue
            if (p0){
                // B0..B2 already in flight (3 groups); add one A group for chunks 0..2
                #pragma unroll
                for (int p=0;p<STAGES-1;p++) load_A(smbase, p, p, m_t, t, Hcur, tid);
                CP_COMMIT();                                  // group 4
            } else {
                #pragma unroll
                for (int p=0;p<STAGES-1;p++){
                    load_B(smbase, p, p, n_t, tid);
                    load_A(smbase, p, p, m_t, t, Hcur, tid);
                    CP_COMMIT();
                }
            }

            for (int kc=0; kc<NCHUNK; ++kc){
                if (kc + STAGES-1 < NCHUNK){
                    int st = (kc + STAGES-1) & (STAGES-1);
                    load_B(smbase, st, kc+STAGES-1, n_t, tid);
                    load_A(smbase, st, kc+STAGES-1, m_t, t, Hcur, tid);
                    CP_COMMIT();
                    if (p0 && kc == 0){
                        asm volatile("cp.async.wait_group 1;" ::: "memory");
                    } else {
                        asm volatile("cp.async.wait_group 3;" ::: "memory");
                    }
                } else {
                    asm volatile("cp.async.wait_group 0;" ::: "memory");
                }
                __syncthreads();

                const unsigned* Bs = smem_u + (kc & (STAGES-1))*STGW;
                const unsigned* As = Bs + BBLKW;

                // A frags: 4x LDS.128 (rows wm*16+grp, +8), conflict-free
                int r0 = (wm*16 + grp)*ASTRW + quad*8;
                uint4 alo0 = *reinterpret_cast<const uint4*>(As + r0);
                uint4 ahi0 = *reinterpret_cast<const uint4*>(As + r0 + 4);
                uint4 alo1 = *reinterpret_cast<const uint4*>(As + r0 + 8*ASTRW);
                uint4 ahi1 = *reinterpret_cast<const uint4*>(As + r0 + 8*ASTRW + 4);
                // B frags: 8x LDS.128, xor-swizzled, conflict-free
                uint4 blo[4], bhi[4];
                #pragma unroll
                for (int ni=0; ni<4; ni++){
                    int cc = wn*32 + ni*8 + grp;
                    blo[ni] = *reinterpret_cast<const uint4*>(Bs + quad*1024 + ((cc*8    ) ^ swz));
                    bhi[ni] = *reinterpret_cast<const uint4*>(Bs + quad*1024 + ((cc*8 + 4) ^ swz));
                }
                #pragma unroll
                for (int s=0; s<4; s++){
                    unsigned a0 = u4c(alo0,s), a1 = u4c(alo1,s);
                    unsigned a2 = u4c(ahi0,s), a3 = u4c(ahi1,s);
                    #pragma unroll
                    for (int ni=0; ni<4; ni++)
                        mma16(c[ni], a0, a1, a2, a3, u4c(blo[ni],s), u4c(bhi[ni],s));
                }
            }

            // Ensure ALL warps have finished their final-chunk smem reads before
            // the gate tile overwrites any stage region (robustness barrier).
            __syncthreads();

            // stage gate tile [64 x 128] fp32 in smem (stage-2 region, dead data)
            {
                int r = wm*16 + grp;
                #pragma unroll
                for (int ni=0;ni<4;ni++){
                    int cl = wn*32 + ni*8 + quad*2;
                    *reinterpret_cast<float2*>(gsm + r*128 + cl)     = make_float2(c[ni][0], c[ni][1]);
                    *reinterpret_cast<float2*>(gsm + (r+8)*128 + cl) = make_float2(c[ni][2], c[ni][3]);
                }
            }
            __syncthreads();

            // LSTM cell update; C in registers, H (fp16 pair, permuted) to global
            const int hw = (n_t>>1)*32 + p_from_w((n_t&1)*16 + hp);
            #pragma unroll
            for (int s=0;s<2;s++){
                int row = 2*bg + s;
                float4 ga = *reinterpret_cast<const float4*>(gsm + row*128 + 8*hp);
                float4 gb = *reinterpret_cast<const float4*>(gsm + row*128 + 8*hp + 4);
                float Cn0 = sigf(ga.y)*Cst[tl][s][0] + sigf(ga.x)*tanhf(ga.w);
                float Cn1 = sigf(gb.y)*Cst[tl][s][1] + sigf(gb.x)*tanhf(gb.w);
                Cst[tl][s][0] = Cn0; Cst[tl][s][1] = Cn1;
                float Hv0 = sigf(ga.z)*tanhf(Cn0);
                float Hv1 = sigf(gb.z)*tanhf(Cn1);
                Hnxt[(size_t)(m_t*MT + row)*HROWW + hw] = packh2(Hv0, Hv1);
            }
            __syncthreads();
        }

        // prefetch next step's weights for tiles[0] BEFORE the grid barrier
        if (t + 1 < SEQ){
            int n0 = tiles[0] & 31;
            #pragma unroll
            for (int p=0;p<STAGES-1;p++){
                load_B(smbase, p, p, n0, tid);
                CP_COMMIT();
            }
            pre = true;
        } else pre = false;

        // ---- grid barrier ----
        __threadfence();
        __syncthreads();
        if (tid == 0){
            unsigned v;
            if (grouped){
                atomicAdd(&d_barc[mygrp], 1u);
                unsigned target = (unsigned)(t+1) * 32u;
                do { asm volatile("ld.acquire.gpu.u32 %0, [%1];" : "=r"(v) : "l"(&d_barc[mygrp])); }
                while (v < target);
            } else {
                atomicAdd(&d_barg, 1u);
                unsigned target = (unsigned)(t+1) * (unsigned)G;
                do { asm volatile("ld.acquire.gpu.u32 %0, [%1];" : "=r"(v) : "l"(&d_barg)); }
                while (v < target);
            }
        }
        __syncthreads();
    }

    // ---- dense head: out[256,2] = H_final @ dense_w + dense_b (de-permute k) ----
    const unsigned* Hf = d_Hb[SEQ & 1];
    for (int tl=0; tl<ntl; ++tl){
        int tile = tiles[tl];
        if ((tile & 31) != 0) continue;
        int m_t = tile >> 5;
        if (tid < 128){
            int r  = m_t*MT + (tid >> 1);
            int cx = tid & 1;
            float sum = db[cx];
            const __half2* hr = reinterpret_cast<const __half2*>(Hf + (size_t)r*HROWW);
            for (int wp=0; wp<HROWW; ++wp){
                int group = wp>>5, pl = wp&31;
                int q = pl>>3, hf = (pl>>2)&1, s = pl&3;
                int k = group*64 + 2*(s*8 + q + hf*4);
                __half2 hv = hr[wp];
                sum += __low2float(hv)*dw[k*2 + cx] + __high2float(hv)*dw[(k+1)*2 + cx];
            }
            out[r*2 + cx] = sum;
        }
    }
}

// ---------------- launcher ----------------
extern "C" void kernel_launch(void* const* d_in, const int* in_sizes, int n_in,
                              void* d_out, int out_size)
{
    const int*   tokens = (const int*)  d_in[0];
    const float* H0     = (const float*)d_in[1];
    const float* C0v    = (const float*)d_in[2];
    const float* Wxi = (const float*)d_in[3],  *Whi = (const float*)d_in[4],  *bi = (const float*)d_in[5];
    const float* Wxf = (const float*)d_in[6],  *Whf = (const float*)d_in[7],  *bf = (const float*)d_in[8];
    const float* Wxo = (const float*)d_in[9],  *Who = (const float*)d_in[10], *bo = (const float*)d_in[11];
    const float* Wxc = (const float*)d_in[12], *Whc = (const float*)d_in[13], *bc = (const float*)d_in[14];
    const float* emb = (const float*)d_in[15];
    const float* dw  = (const float*)d_in[16];
    const float* db  = (const float*)d_in[17];
    float* out = (float*)d_out;

    int dev = 0; cudaGetDevice(&dev);
    int sms = 0; cudaDeviceGetAttribute(&sms, cudaDevAttrMultiProcessorCount, dev);
    int grid = (sms < NTILES) ? sms : NTILES;   // 128 on sm_100a (148 SMs) -> 1 tile/CTA
    if (grid < 64) grid = 64;

    cudaFuncSetAttribute(lstm_persist, cudaFuncAttributeMaxDynamicSharedMemorySize,
                         SMW*(int)sizeof(unsigned));

    k_init   <<<(BATCH*HROWW + 255)/256, 256>>>(H0);
    k_embed  <<<(SEQ*BATCH*XROWW + 255)/256, 256>>>(tokens, emb);
    {
        size_t nw = (size_t)NCHUNK*32*BBLKW;
        k_weights<<<(unsigned)((nw + 255)/256), 256>>>(Wxi,Whi,bi, Wxf,Whf,bf, Wxo,Who,bo, Wxc,Whc,bc);
    }
    lstm_persist<<<grid, THREADS, SMW*(int)sizeof(unsigned)>>>(C0v, dw, db, out);
}

// round 9
// speedup vs baseline: 2.6144x; 1.4611x over previous
#include <cuda_runtime.h>
#include <cuda_fp16.h>
#include <cstdint>
#include <cstddef>

// ---------------- dims ----------------
#define BATCH   256
#define SEQ     512
#define EMBD    100
#define HID     1024
#define THREADS 512
#define NHC     36        // half-chunks of K=32 (32 H + 4 X), K total 1152
#define GST     34        // gate smem row stride (floats)
#define GGT     (64*GST)  // per-gate block (2176 floats)
#define DSMEM   122880    // force 1 CTA/SM (gsm uses 34816B of it)

// ---------------- device scratch (fragment-order images) ----------------
// B (weights):  [kc18][n_t32][wn4][j4][pair2][lane32] uint4   (9.4 MB)
__device__ uint4 d_Wb[(size_t)18*32*4*4*2*32];
// A (X):        [t512][m_t4][rowblk4][kx2][j4][lane32] uint4  (33.6 MB)
__device__ uint4 d_Xa[(size_t)SEQ*4*4*2*4*32];
// A (H state):  [buf2][m_t4][rowblk4][kc16][j4][lane32] uint4 (0.5 MB each)
__device__ uint4 d_Ha[2][(size_t)4*4*16*4*32];
__device__ float d_biasp[4096];     // [g][1024]
__device__ unsigned d_barc[4];      // per-m_t grid-barrier counters

// ---------------- helpers ----------------
__device__ __forceinline__ float sigf(float x){ return 1.0f/(1.0f + __expf(-x)); }
__device__ __forceinline__ unsigned packh2(float a, float b){
    __half2 h = __floats2half2_rn(a, b);
    return *reinterpret_cast<unsigned*>(&h);
}
__device__ __forceinline__ void mma16(float c[4], unsigned a0, unsigned a1, unsigned a2, unsigned a3,
                                      unsigned b0, unsigned b1){
    asm volatile("mma.sync.aligned.m16n8k16.row.col.f32.f16.f16.f32 "
        "{%0,%1,%2,%3}, {%4,%5,%6,%7}, {%8,%9}, {%0,%1,%2,%3};"
        : "+f"(c[0]), "+f"(c[1]), "+f"(c[2]), "+f"(c[3])
        : "r"(a0), "r"(a1), "r"(a2), "r"(a3), "r"(b0), "r"(b1));
}

// ---------------- setup kernels ----------------
// H0 -> A-fragment image (buf 0). u32 i: [m_t][rowblk][kc][j][lane][c]
__global__ void k_init(const float* __restrict__ H0){
    int i = blockIdx.x*blockDim.x + threadIdx.x;
    if (i < 4) d_barc[i] = 0;
    if (i >= 4*4*16*4*32*4) return;
    int c = i&3, lane = (i>>2)&31, j = (i>>7)&3, kc = (i>>9)&15;
    int rowblk = (i>>13)&3, m_t = (i>>15)&3;
    int b = m_t*64 + rowblk*16 + (c&1)*8 + (lane>>2);
    int k = kc*64 + j*16 + (c>>1)*8 + (lane&3)*2;
    reinterpret_cast<unsigned*>(d_Ha[0])[i] =
        packh2(H0[(size_t)b*HID + k], H0[(size_t)b*HID + k + 1]);
}

// tokens/emb -> X A-fragment images. u32 i: [t][m_t][rowblk][kx][j][lane][c]
__global__ void k_embed(const int* __restrict__ tokens, const float* __restrict__ emb){
    int i = blockIdx.x*blockDim.x + threadIdx.x;
    if (i >= SEQ*4*4*2*4*32*4) return;
    int c = i&3, lane = (i>>2)&31, j = (i>>7)&3, kx = (i>>9)&1;
    int rowblk = (i>>10)&3, m_t = (i>>12)&3, t = i>>14;
    int b = m_t*64 + rowblk*16 + (c&1)*8 + (lane>>2);
    int e = kx*64 + j*16 + (c>>1)*8 + (lane&3)*2;
    float f0 = 0.0f, f1 = 0.0f;
    if (e < EMBD){
        int tok = tokens[b*SEQ + t];
        f0 = emb[(size_t)tok*EMBD + e];
        if (e + 1 < EMBD) f1 = emb[(size_t)tok*EMBD + e + 1];
    }
    reinterpret_cast<unsigned*>(d_Xa)[i] = packh2(f0, f1);
}

// weights -> B-fragment image. u32 i: [kc][n_t][wn][j][pair][lane][c]
__global__ void k_weights(
    const float* __restrict__ Wxi, const float* __restrict__ Whi,
    const float* __restrict__ Wxf, const float* __restrict__ Whf,
    const float* __restrict__ Wxo, const float* __restrict__ Who,
    const float* __restrict__ Wxc, const float* __restrict__ Whc)
{
    int i = blockIdx.x*blockDim.x + threadIdx.x;
    if (i >= 18*32*4*4*2*32*4) return;
    int c = i&3, lane = (i>>2)&31, pair = (i>>7)&1, j = (i>>8)&3;
    int wn = (i>>10)&3, n_t = (i>>12)&31, kc = i>>17;
    int n8 = pair*2 + (c>>1), khalf = c&1;
    int k = kc*64 + j*16 + khalf*8 + (lane&3)*2;
    int h = n_t*32 + n8*8 + (lane>>2);
    int g = wn;
    const float* Wh = (g==0)?Whi:(g==1)?Whf:(g==2)?Who:Whc;
    const float* Wx = (g==0)?Wxi:(g==1)?Wxf:(g==2)?Wxo:Wxc;
    float f0 = 0.0f, f1 = 0.0f;
    if (k < 1024)             f0 = Wh[(size_t)k*HID + h];
    else if (k < 1024+EMBD)   f0 = Wx[(size_t)(k-1024)*HID + h];
    int k1 = k + 1;
    if (k1 < 1024)            f1 = Wh[(size_t)k1*HID + h];
    else if (k1 < 1024+EMBD)  f1 = Wx[(size_t)(k1-1024)*HID + h];
    reinterpret_cast<unsigned*>(d_Wb)[i] = packh2(f0, f1);
}

__global__ void k_bias(const float* __restrict__ bi, const float* __restrict__ bf,
                       const float* __restrict__ bo, const float* __restrict__ bc){
    int i = blockIdx.x*blockDim.x + threadIdx.x;
    if (i >= 4096) return;
    int g = i >> 10, h = i & 1023;
    d_biasp[i] = (g==0?bi:g==1?bf:g==2?bo:bc)[h];
}

// ---------------- persistent direct-LDG LSTM scan ----------------
__global__ void __launch_bounds__(THREADS,1)
lstm_dg(const float* __restrict__ C0, const float* __restrict__ dw,
        const float* __restrict__ db, float* __restrict__ out)
{
    extern __shared__ float gsm[];     // [4 gates][64 rows][GST]
    const int tid  = threadIdx.x;
    const int warp = tid >> 5, lane = tid & 31;
    const int wm   = warp >> 2, wn = warp & 3;
    const int grp  = lane >> 2, quad = lane & 3;
    const int m_t  = blockIdx.x >> 5, n_t = blockIdx.x & 31;

    // fragment-stream base pointers
    const uint4* Bb = d_Wb + (size_t)(n_t*4 + wn)*256 + lane;
    const uint4* A0 = d_Ha[0] + (size_t)(m_t*4 + wm)*2048 + lane;
    const uint4* A1 = d_Ha[1] + (size_t)(m_t*4 + wm)*2048 + lane;

    // epilogue ownership: iter it -> (b_local = tid>>4 + 32*it, h pair hp = tid&15)
    const int b0l = tid >> 4, hp = tid & 15;
    const int h_loc0 = hp*2;
    const int hg = n_t*32 + h_loc0;
    unsigned woff[2];
    {
        int kc = hg>>6, kl = hg&63, j = kl>>4, rem = kl&15;
        int kh = rem>>3, qd = (rem&7)>>1;
        #pragma unroll
        for (int it = 0; it < 2; it++){
            int b = b0l + it*32;
            int rb = b>>4, row = b&15, r8 = row>>3, g7 = row&7;
            woff[it] = (unsigned)(((((m_t*4+rb)*16 + kc)*4 + j)*32 + (g7*4+qd))*4 + kh*2 + r8);
        }
    }
    float Cst[2][2];
    #pragma unroll
    for (int it = 0; it < 2; it++){
        int b = m_t*64 + b0l + it*32;
        Cst[it][0] = C0[(size_t)b*HID + hg];
        Cst[it][1] = C0[(size_t)b*HID + hg + 1];
    }

    float acc[4][4];

    for (int t = 0; t < SEQ; ++t){
        const uint4* Ah = (t & 1) ? A1 : A0;
        unsigned* Hn = reinterpret_cast<unsigned*>((t & 1) ? d_Ha[0] : d_Ha[1]);
        const uint4* Xb = d_Xa + ((size_t)(t*4 + m_t)*4 + wm)*256 + lane;

        #pragma unroll
        for (int n8 = 0; n8 < 4; n8++)
            acc[n8][0] = acc[n8][1] = acc[n8][2] = acc[n8][3] = 0.0f;

        // register double-buffered fragment stream, barrier-free
        uint4 av[2][2], bv[2][4];
        av[0][0] = Ah[0];  av[0][1] = Ah[32];
        bv[0][0] = Bb[0];  bv[0][1] = Bb[32]; bv[0][2] = Bb[64]; bv[0][3] = Bb[96];

        #pragma unroll 4
        for (int hc = 0; hc < NHC; hc++){
            int cb = hc & 1, nb = cb ^ 1;
            int hn = hc + 1;
            if (hn < NHC){
                const uint4* ap = (hn < 32) ? (Ah + hn*64) : (Xb + (hn-32)*64);
                av[nb][0] = ap[0];  av[nb][1] = ap[32];
                const uint4* bp = Bb + (size_t)(hn>>1)*32768 + (hn&1)*128;
                bv[nb][0] = bp[0];  bv[nb][1] = bp[32];
                bv[nb][2] = bp[64]; bv[nb][3] = bp[96];
            }
            #pragma unroll
            for (int jj = 0; jj < 2; jj++){
                uint4 a  = av[cb][jj];
                uint4 p0 = bv[cb][jj*2], p1 = bv[cb][jj*2+1];
                mma16(acc[0], a.x,a.y,a.z,a.w, p0.x,p0.y);
                mma16(acc[1], a.x,a.y,a.z,a.w, p0.z,p0.w);
                mma16(acc[2], a.x,a.y,a.z,a.w, p1.x,p1.y);
                mma16(acc[3], a.x,a.y,a.z,a.w, p1.z,p1.w);
            }
        }

        // gate exchange: acc -> gsm [gate wn][row][h_l]
        {
            int r0 = wm*16 + grp;
            #pragma unroll
            for (int n8 = 0; n8 < 4; n8++){
                int nl = n8*8 + quad*2;
                *reinterpret_cast<float2*>(&gsm[wn*GGT + r0*GST + nl])
                    = make_float2(acc[n8][0], acc[n8][1]);
                *reinterpret_cast<float2*>(&gsm[wn*GGT + (r0+8)*GST + nl])
                    = make_float2(acc[n8][2], acc[n8][3]);
            }
        }
        __syncthreads();

        // cell update; H (fp16 pair) written into next step's fragment image
        {
            float bi0 = d_biasp[hg],        bi1 = d_biasp[hg+1];
            float bf0 = d_biasp[1024+hg],   bf1 = d_biasp[1024+hg+1];
            float bo0 = d_biasp[2048+hg],   bo1 = d_biasp[2048+hg+1];
            float bc0 = d_biasp[3072+hg],   bc1 = d_biasp[3072+hg+1];
            #pragma unroll
            for (int it = 0; it < 2; it++){
                int b = b0l + it*32;
                float2 gi = *reinterpret_cast<float2*>(&gsm[        b*GST + h_loc0]);
                float2 gf = *reinterpret_cast<float2*>(&gsm[GGT   + b*GST + h_loc0]);
                float2 go = *reinterpret_cast<float2*>(&gsm[2*GGT + b*GST + h_loc0]);
                float2 gc = *reinterpret_cast<float2*>(&gsm[3*GGT + b*GST + h_loc0]);
                float Cn0 = sigf(gf.x+bf0)*Cst[it][0] + sigf(gi.x+bi0)*tanhf(gc.x+bc0);
                float Cn1 = sigf(gf.y+bf1)*Cst[it][1] + sigf(gi.y+bi1)*tanhf(gc.y+bc1);
                Cst[it][0] = Cn0; Cst[it][1] = Cn1;
                float Hv0 = sigf(go.x+bo0)*tanhf(Cn0);
                float Hv1 = sigf(go.y+bo1)*tanhf(Cn1);
                Hn[woff[it]] = packh2(Hv0, Hv1);
            }
        }

        // grid barrier (per-m_t group of 32 CTAs)
        __threadfence();
        __syncthreads();
        if (tid == 0){
            atomicAdd(&d_barc[m_t], 1u);
            unsigned target = (unsigned)(t+1)*32u, v;
            do { asm volatile("ld.acquire.gpu.u32 %0, [%1];" : "=r"(v) : "l"(&d_barc[m_t])); }
            while (v < target);
        }
        __syncthreads();
    }

    // ---- dense head: out[256,2] = H_final @ dense_w + dense_b ----
    if (n_t == 0 && tid < 128){
        int rl = tid >> 1, cx = tid & 1;
        const unsigned* Hf = reinterpret_cast<const unsigned*>(d_Ha[0]); // t=511 wrote buf 0
        float sum = db[cx];
        int rb = rl>>4, row = rl&15, r8 = row>>3, g7 = row&7;
        for (int wp = 0; wp < 512; wp++){
            int h = wp*2;
            int kc = h>>6, kl = h&63, j = kl>>4, rem = kl&15;
            int kh = rem>>3, qd = (rem&7)>>1;
            unsigned off = (unsigned)(((((m_t*4+rb)*16 + kc)*4 + j)*32 + (g7*4+qd))*4 + kh*2 + r8);
            unsigned v = Hf[off];
            __half2 hv = *reinterpret_cast<__half2*>(&v);
            sum += __low2float(hv)*dw[h*2 + cx] + __high2float(hv)*dw[(h+1)*2 + cx];
        }
        out[(m_t*64 + rl)*2 + cx] = sum;
    }
}

// ---------------- launcher ----------------
extern "C" void kernel_launch(void* const* d_in, const int* in_sizes, int n_in,
                              void* d_out, int out_size)
{
    const int*   tokens = (const int*)  d_in[0];
    const float* H0     = (const float*)d_in[1];
    const float* C0v    = (const float*)d_in[2];
    const float* Wxi = (const float*)d_in[3],  *Whi = (const float*)d_in[4],  *bi = (const float*)d_in[5];
    const float* Wxf = (const float*)d_in[6],  *Whf = (const float*)d_in[7],  *bf = (const float*)d_in[8];
    const float* Wxo = (const float*)d_in[9],  *Who = (const float*)d_in[10], *bo = (const float*)d_in[11];
    const float* Wxc = (const float*)d_in[12], *Whc = (const float*)d_in[13], *bc = (const float*)d_in[14];
    const float* emb = (const float*)d_in[15];
    const float* dw  = (const float*)d_in[16];
    const float* db  = (const float*)d_in[17];
    float* out = (float*)d_out;

    cudaFuncSetAttribute(lstm_dg, cudaFuncAttributeMaxDynamicSharedMemorySize, DSMEM);

    k_init   <<<(4*4*16*4*32*4 + 255)/256, 256>>>(H0);
    k_embed  <<<(SEQ*4*4*2*4*32*4 + 255)/256, 256>>>(tokens, emb);
    k_weights<<<(18*32*4*4*2*32*4 + 255)/256, 256>>>(Wxi,Whi, Wxf,Whf, Wxo,Who, Wxc,Whc);
    k_bias   <<<16, 256>>>(bi, bf, bo, bc);
    lstm_dg<<<128, THREADS, DSMEM>>>(C0v, dw, db, out);
}

// round 11
// speedup vs baseline: 3.0666x; 1.1730x over previous
#include <cuda_runtime.h>
#include <cuda_fp16.h>
#include <cstdint>
#include <cstddef>

// ---------------- dims ----------------
#define BATCH   256
#define SEQ     512
#define EMBD    100
#define HID     1024
#define THREADS 512
#define GST     34          // gate smem row stride (floats)
#define GGT     (64*GST)    // per-gate block (2176 floats)
#define GKG     (4*GGT)     // per-k-group block (8704 floats)
#define DSMEM   122880      // force 1 CTA/SM (gsm uses 69632B of it)

// ---------------- device scratch (fragment-order images) ----------------
// B (weights): [kc18][n_t32][wn4][j4][pair2][lane32] uint4  (9.4 MB) - unchanged from R9
__device__ uint4 d_Wb[(size_t)18*32*4*4*2*32];
// A (X):       [t512][m_t4][rb2][xk4][f4][lane32] uint4     (33.6 MB), Mw=32 frag order
__device__ uint4 d_Xa[(size_t)SEQ*4*2*4*4*32];
// A (H state): [buf2][m_t4][rb2][hk32][f4][lane32] uint4    (0.5 MB each)
__device__ uint4 d_Ha[2][(size_t)4*2*32*4*32];
__device__ float d_biasp[4096];     // [g][1024]
__device__ unsigned d_barc[4];      // per-m_t grid-barrier counters

// ---------------- helpers ----------------
__device__ __forceinline__ float sigf(float x){ return 1.0f/(1.0f + __expf(-x)); }
__device__ __forceinline__ unsigned packh2(float a, float b){
    __half2 h = __floats2half2_rn(a, b);
    return *reinterpret_cast<unsigned*>(&h);
}
__device__ __forceinline__ void mma16(float c[4], unsigned a0, unsigned a1, unsigned a2, unsigned a3,
                                      unsigned b0, unsigned b1){
    asm volatile("mma.sync.aligned.m16n8k16.row.col.f32.f16.f16.f32 "
        "{%0,%1,%2,%3}, {%4,%5,%6,%7}, {%8,%9}, {%0,%1,%2,%3};"
        : "+f"(c[0]), "+f"(c[1]), "+f"(c[2]), "+f"(c[3])
        : "r"(a0), "r"(a1), "r"(a2), "r"(a3), "r"(b0), "r"(b1));
}

// ---------------- setup kernels ----------------
// H0 -> A-frag image (buf 0). u32 i: [m_t2b][rb1b][hk5b][f2b][lane5b][c2b]
__global__ void k_init(const float* __restrict__ H0){
    int i = blockIdx.x*blockDim.x + threadIdx.x;
    if (i < 4) d_barc[i] = 0;
    if (i >= 4*2*32*4*32*4) return;
    int c = i&3, l = (i>>2)&31, f = (i>>7)&3, hk = (i>>9)&31;
    int rb = (i>>14)&1, m_t = (i>>15)&3;
    int b = m_t*64 + rb*32 + (f>>1)*16 + (c&1)*8 + (l>>2);
    int k = hk*32 + (f&1)*16 + ((c>>1)&1)*8 + (l&3)*2;
    reinterpret_cast<unsigned*>(d_Ha[0])[i] =
        packh2(H0[(size_t)b*HID + k], H0[(size_t)b*HID + k + 1]);
}

// tokens/emb -> X A-frag images. u32 i: [t][m_t][rb][xk][f][lane][c]
__global__ void k_embed(const int* __restrict__ tokens, const float* __restrict__ emb){
    int i = blockIdx.x*blockDim.x + threadIdx.x;
    if (i >= SEQ*4*2*4*4*32*4) return;
    int c = i&3, l = (i>>2)&31, f = (i>>7)&3, xk = (i>>9)&3;
    int rb = (i>>11)&1, m_t = (i>>12)&3, t = i>>14;
    int b = m_t*64 + rb*32 + (f>>1)*16 + (c&1)*8 + (l>>2);
    int e = xk*32 + (f&1)*16 + ((c>>1)&1)*8 + (l&3)*2;
    float f0 = 0.0f, f1 = 0.0f;
    if (e < EMBD){
        int tok = tokens[b*SEQ + t];
        f0 = emb[(size_t)tok*EMBD + e];
        if (e + 1 < EMBD) f1 = emb[(size_t)tok*EMBD + e + 1];
    }
    reinterpret_cast<unsigned*>(d_Xa)[i] = packh2(f0, f1);
}

// weights -> B-frag image (identical to R9). u32 i: [kc][n_t][wn][j][pair][lane][c]
__global__ void k_weights(
    const float* __restrict__ Wxi, const float* __restrict__ Whi,
    const float* __restrict__ Wxf, const float* __restrict__ Whf,
    const float* __restrict__ Wxo, const float* __restrict__ Who,
    const float* __restrict__ Wxc, const float* __restrict__ Whc)
{
    int i = blockIdx.x*blockDim.x + threadIdx.x;
    if (i >= 18*32*4*4*2*32*4) return;
    int c = i&3, lane = (i>>2)&31, pair = (i>>7)&1, j = (i>>8)&3;
    int wn = (i>>10)&3, n_t = (i>>12)&31, kc = i>>17;
    int n8 = pair*2 + (c>>1), khalf = c&1;
    int k = kc*64 + j*16 + khalf*8 + (lane&3)*2;
    int h = n_t*32 + n8*8 + (lane>>2);
    int g = wn;
    const float* Wh = (g==0)?Whi:(g==1)?Whf:(g==2)?Who:Whc;
    const float* Wx = (g==0)?Wxi:(g==1)?Wxf:(g==2)?Wxo:Wxc;
    float f0 = 0.0f, f1 = 0.0f;
    if (k < 1024)             f0 = Wh[(size_t)k*HID + h];
    else if (k < 1024+EMBD)   f0 = Wx[(size_t)(k-1024)*HID + h];
    int k1 = k + 1;
    if (k1 < 1024)            f1 = Wh[(size_t)k1*HID + h];
    else if (k1 < 1024+EMBD)  f1 = Wx[(size_t)(k1-1024)*HID + h];
    reinterpret_cast<unsigned*>(d_Wb)[i] = packh2(f0, f1);
}

__global__ void k_bias(const float* __restrict__ bi, const float* __restrict__ bf,
                       const float* __restrict__ bo, const float* __restrict__ bc){
    int i = blockIdx.x*blockDim.x + threadIdx.x;
    if (i >= 4096) return;
    int g = i >> 10, h = i & 1023;
    d_biasp[i] = (g==0?bi:g==1?bf:g==2?bo:bc)[h];
}

// ---------------- persistent split-K direct-LDG LSTM scan ----------------
__global__ void __launch_bounds__(THREADS,1)
lstm_dg(const float* __restrict__ C0, const float* __restrict__ dw,
        const float* __restrict__ db, float* __restrict__ out)
{
    extern __shared__ float gsm[];     // [2 kg][4 gates][64 rows][GST]
    const int tid  = threadIdx.x;
    const int warp = tid >> 5, lane = tid & 31;
    const int kg   = warp >> 3;        // k-group 0/1 (K halves of 576)
    const int wg   = warp & 7;
    const int wm   = wg >> 2, wn = wg & 3;   // 2(M:32) x 4(N:32) within group
    const int grp  = lane >> 2, quad = lane & 3;
    const int m_t  = blockIdx.x >> 5, n_t = blockIdx.x & 31;
    const int hc0  = kg*18;            // first half-chunk of this group

    // fragment-stream base pointers
    const uint4* Bb = d_Wb + (size_t)(n_t*4 + wn)*256 + lane;
    const uint4* A0 = d_Ha[0] + (size_t)(m_t*2 + wm)*4096 + lane;
    const uint4* A1 = d_Ha[1] + (size_t)(m_t*2 + wm)*4096 + lane;

    // epilogue ownership: thread -> h-pair hp, rows b0l and b0l+32
    const int b0l = tid >> 4, hp = tid & 15;
    const int hl  = hp*2;                    // h within 32-slice (even)
    const int hg  = n_t*32 + hl;             // global h
    unsigned woff[2];
    {
        int hk = hg >> 5;
        int kk = hl & 15, ki = hl >> 4, chi = kk >> 3, qd = (kk & 7) >> 1;
        #pragma unroll
        for (int it = 0; it < 2; it++){
            int b = b0l + it*32;
            int rb = b >> 5, r32 = b & 31, mi = r32 >> 4, r16 = r32 & 15;
            int c = (r16 >> 3) + chi*2;
            int l = (r16 & 7)*4 + qd;
            int f = mi*2 + ki;
            woff[it] = (unsigned)(((((m_t*2+rb)*32 + hk)*4 + f)*32 + l)*4 + c);
        }
    }
    float Cst[2][2];
    #pragma unroll
    for (int it = 0; it < 2; it++){
        int b = m_t*64 + b0l + it*32;
        Cst[it][0] = C0[(size_t)b*HID + hg];
        Cst[it][1] = C0[(size_t)b*HID + hg + 1];
    }

    float acc[2][4][4];   // [mi][n8][c]

    for (int t = 0; t < SEQ; ++t){
        const uint4* Ah = (t & 1) ? A1 : A0;
        unsigned* Hn = reinterpret_cast<unsigned*>((t & 1) ? d_Ha[0] : d_Ha[1]);
        const uint4* Xb = d_Xa + ((size_t)((t*4 + m_t)*2 + wm))*512 + lane;

        #pragma unroll
        for (int mi = 0; mi < 2; mi++)
            #pragma unroll
            for (int n8 = 0; n8 < 4; n8++)
                acc[mi][n8][0] = acc[mi][n8][1] = acc[mi][n8][2] = acc[mi][n8][3] = 0.0f;

        // register double-buffered fragment stream over this group's 18 half-chunks
        uint4 av[2][4], bv[2][4];
        {
            const uint4* ap = (hc0 < 32) ? (Ah + hc0*128) : (Xb + (hc0-32)*128);
            av[0][0] = ap[0];  av[0][1] = ap[32]; av[0][2] = ap[64]; av[0][3] = ap[96];
            const uint4* bp = Bb + (size_t)(hc0>>1)*32768 + (hc0&1)*128;
            bv[0][0] = bp[0];  bv[0][1] = bp[32]; bv[0][2] = bp[64]; bv[0][3] = bp[96];
        }

        #pragma unroll 2
        for (int i = 0; i < 18; i++){
            int cb = i & 1, nb = cb ^ 1;
            int hn = hc0 + i + 1;
            if (i + 1 < 18){
                const uint4* ap = (hn < 32) ? (Ah + hn*128) : (Xb + (hn-32)*128);
                av[nb][0] = ap[0];  av[nb][1] = ap[32]; av[nb][2] = ap[64]; av[nb][3] = ap[96];
                const uint4* bp = Bb + (size_t)(hn>>1)*32768 + (hn&1)*128;
                bv[nb][0] = bp[0];  bv[nb][1] = bp[32]; bv[nb][2] = bp[64]; bv[nb][3] = bp[96];
            }
            #pragma unroll
            for (int ki = 0; ki < 2; ki++){
                uint4 b0 = bv[cb][ki*2], b1 = bv[cb][ki*2+1];
                #pragma unroll
                for (int mi = 0; mi < 2; mi++){
                    uint4 a = av[cb][mi*2 + ki];
                    mma16(acc[mi][0], a.x,a.y,a.z,a.w, b0.x, b0.y);
                    mma16(acc[mi][1], a.x,a.y,a.z,a.w, b0.z, b0.w);
                    mma16(acc[mi][2], a.x,a.y,a.z,a.w, b1.x, b1.y);
                    mma16(acc[mi][3], a.x,a.y,a.z,a.w, b1.z, b1.w);
                }
            }
        }

        // stage partial gates: gsm[kg][gate wn][row][h_l]
        {
            float* gb = gsm + kg*GKG + wn*GGT;
            #pragma unroll
            for (int mi = 0; mi < 2; mi++){
                int r0 = wm*32 + mi*16 + grp;
                #pragma unroll
                for (int n8 = 0; n8 < 4; n8++){
                    int nl = n8*8 + quad*2;
                    *reinterpret_cast<float2*>(&gb[r0*GST + nl])
                        = make_float2(acc[mi][n8][0], acc[mi][n8][1]);
                    *reinterpret_cast<float2*>(&gb[(r0+8)*GST + nl])
                        = make_float2(acc[mi][n8][2], acc[mi][n8][3]);
                }
            }
        }
        __syncthreads();

        // cell update: sum the two K-halves + bias; H into next step's frag image
        {
            float bi0 = d_biasp[hg],        bi1 = d_biasp[hg+1];
            float bf0 = d_biasp[1024+hg],   bf1 = d_biasp[1024+hg+1];
            float bo0 = d_biasp[2048+hg],   bo1 = d_biasp[2048+hg+1];
            float bc0 = d_biasp[3072+hg],   bc1 = d_biasp[3072+hg+1];
            #pragma unroll
            for (int it = 0; it < 2; it++){
                int b = b0l + it*32;
                float2 gi0 = *reinterpret_cast<float2*>(&gsm[        b*GST + hl]);
                float2 gf0 = *reinterpret_cast<float2*>(&gsm[GGT   + b*GST + hl]);
                float2 go0 = *reinterpret_cast<float2*>(&gsm[2*GGT + b*GST + hl]);
                float2 gc0 = *reinterpret_cast<float2*>(&gsm[3*GGT + b*GST + hl]);
                float2 gi1 = *reinterpret_cast<float2*>(&gsm[GKG         + b*GST + hl]);
                float2 gf1 = *reinterpret_cast<float2*>(&gsm[GKG + GGT   + b*GST + hl]);
                float2 go1 = *reinterpret_cast<float2*>(&gsm[GKG + 2*GGT + b*GST + hl]);
                float2 gc1 = *reinterpret_cast<float2*>(&gsm[GKG + 3*GGT + b*GST + hl]);
                float vi0 = gi0.x + gi1.x + bi0, vi1 = gi0.y + gi1.y + bi1;
                float vf0 = gf0.x + gf1.x + bf0, vf1 = gf0.y + gf1.y + bf1;
                float vo0 = go0.x + go1.x + bo0, vo1 = go0.y + go1.y + bo1;
                float vc0 = gc0.x + gc1.x + bc0, vc1 = gc0.y + gc1.y + bc1;
                float Cn0 = sigf(vf0)*Cst[it][0] + sigf(vi0)*tanhf(vc0);
                float Cn1 = sigf(vf1)*Cst[it][1] + sigf(vi1)*tanhf(vc1);
                Cst[it][0] = Cn0; Cst[it][1] = Cn1;
                float Hv0 = sigf(vo0)*tanhf(Cn0);
                float Hv1 = sigf(vo1)*tanhf(Cn1);
                Hn[woff[it]] = packh2(Hv0, Hv1);
            }
        }

        // grid barrier (per-m_t group of 32 CTAs)
        __threadfence();
        __syncthreads();
        if (tid == 0){
            atomicAdd(&d_barc[m_t], 1u);
            unsigned target = (unsigned)(t+1)*32u, v;
            do { asm volatile("ld.acquire.gpu.u32 %0, [%1];" : "=r"(v) : "l"(&d_barc[m_t])); }
            while (v < target);
        }
        __syncthreads();
    }

    // ---- dense head: out[256,2] = H_final @ dense_w + dense_b (t=511 wrote buf 0) ----
    if (n_t == 0 && tid < 128){
        int rl = tid >> 1, cx = tid & 1;
        const unsigned* Hf = reinterpret_cast<const unsigned*>(d_Ha[0]);
        float sum = db[cx];
        int rb = rl >> 5, r32 = rl & 31, mi = r32 >> 4, r16 = r32 & 15;
        int clo = r16 >> 3, lbase = (r16 & 7)*4;
        for (int h = 0; h < HID; h += 2){
            int hk = h >> 5, h5 = h & 31, ki = h5 >> 4, kk = h5 & 15;
            int chi = kk >> 3, qd = (kk & 7) >> 1;
            int c = clo + chi*2, l = lbase + qd, f = mi*2 + ki;
            unsigned off = (unsigned)(((((m_t*2+rb)*32 + hk)*4 + f)*32 + l)*4 + c);
            unsigned v = Hf[off];
            __half2 hv = *reinterpret_cast<__half2*>(&v);
            sum += __low2float(hv)*dw[h*2 + cx] + __high2float(hv)*dw[(h+1)*2 + cx];
        }
        out[(m_t*64 + rl)*2 + cx] = sum;
    }
}

// ---------------- launcher ----------------
extern "C" void kernel_launch(void* const* d_in, const int* in_sizes, int n_in,
                              void* d_out, int out_size)
{
    const int*   tokens = (const int*)  d_in[0];
    const float* H0     = (const float*)d_in[1];
    const float* C0v    = (const float*)d_in[2];
    const float* Wxi = (const float*)d_in[3],  *Whi = (const float*)d_in[4],  *bi = (const float*)d_in[5];
    const float* Wxf = (const float*)d_in[6],  *Whf = (const float*)d_in[7],  *bf = (const float*)d_in[8];
    const float* Wxo = (const float*)d_in[9],  *Who = (const float*)d_in[10], *bo = (const float*)d_in[11];
    const float* Wxc = (const float*)d_in[12], *Whc = (const float*)d_in[13], *bc = (const float*)d_in[14];
    const float* emb = (const float*)d_in[15];
    const float* dw  = (const float*)d_in[16];
    const float* db  = (const float*)d_in[17];
    float* out = (float*)d_out;

    cudaFuncSetAttribute(lstm_dg, cudaFuncAttributeMaxDynamicSharedMemorySize, DSMEM);

    k_init   <<<(4*2*32*4*32*4 + 255)/256, 256>>>(H0);
    k_embed  <<<(SEQ*4*2*4*4*32*4 + 255)/256, 256>>>(tokens, emb);
    k_weights<<<(18*32*4*4*2*32*4 + 255)/256, 256>>>(Wxi,Whi, Wxf,Whf, Wxo,Who, Wxc,Whc);
    k_bias   <<<16, 256>>>(bi, bf, bo, bc);
    lstm_dg<<<128, THREADS, DSMEM>>>(C0v, dw, db, out);
}